// round 12
// baseline (speedup 1.0000x reference)
#include <cuda_runtime.h>
#include <cuda_fp16.h>

#define NN 50000
#define EE 800000
#define D  128
#define G  8
#define C  10

// ---------------- scratch (static device globals; no allocs allowed) --------
__device__ float  g_in_isqrt[NN];
__device__ __half g_h16A[NN * D];
__device__ __half g_h16B[NN * D];
__device__ __half g_W1hi[D * D];
__device__ __half g_W1lo[D * D];
__device__ __half g_W2hi[D * D];
__device__ __half g_W2lo[D * D];
__device__ float  g_sums[G * D];
__device__ int    g_outcnt[NN];
__device__ int    g_incnt[NN];
__device__ int    g_rowptr[NN + 1];
__device__ int    g_cursor[NN];
__device__ int    g_csr[EE];
__device__ int    g_bsums[256];
__device__ int    g_done;

// ---------------- setup: zero degree arrays + pool sums, convert weights ------
__global__ __launch_bounds__(256)
void k_setup(int* __restrict__ outc, int* __restrict__ inc, int n,
             float* __restrict__ sums,
             const float* __restrict__ W1, const float* __restrict__ W2,
             __half* __restrict__ w1h, __half* __restrict__ w1l,
             __half* __restrict__ w2h, __half* __restrict__ w2l) {
    int i = blockIdx.x * 256 + threadIdx.x;
    if (i == 0) g_done = 0;
    if (i < n) { outc[i] = 0; inc[i] = 0; }
    if (i < G * D) sums[i] = 0.0f;
    if (i < D * D) {
        int k = i >> 7, nn = i & 127;
        float v = W1[i];
        __half hi = __float2half_rn(v);
        w1h[nn * D + k] = hi;
        w1l[nn * D + k] = __float2half_rn(v - __half2float(hi));
        v = W2[i];
        hi = __float2half_rn(v);
        w2h[nn * D + k] = hi;
        w2l[nn * D + k] = __float2half_rn(v - __half2float(hi));
    }
}

// ---------------- degree histograms (int) ------------------------------------
__global__ void k_degcount(const int* __restrict__ ei, int E,
                           int* __restrict__ outc, int* __restrict__ inc) {
    int e = blockIdx.x * blockDim.x + threadIdx.x;
    if (e < E) {
        atomicAdd(&outc[ei[e]], 1);
        atomicAdd(&inc[ei[E + e]], 1);
    }
}

// ---------------- scan helpers -------------------------------------------------
__device__ __forceinline__ int warp_incl_scan(int v, int lane) {
#pragma unroll
    for (int o = 1; o < 32; o <<= 1) {
        int t = __shfl_up_sync(0xffffffffu, v, o);
        if (lane >= o) v += t;
    }
    return v;
}

__device__ __forceinline__ int block_incl_scan(int v, int tid, int* ws) {
    int lane = tid & 31, wid = tid >> 5;
    int s = warp_incl_scan(v, lane);
    if (lane == 31) ws[wid] = s;
    __syncthreads();
    if (wid == 0) {
        int t = (lane < 8) ? ws[lane] : 0;
        t = warp_incl_scan(t, lane);
        if (lane < 8) ws[lane] = t;
    }
    __syncthreads();
    return s + (wid > 0 ? ws[wid - 1] : 0);
}

__global__ __launch_bounds__(256)
void k_scan1(const int* __restrict__ inc, int n, int* __restrict__ bsums) {
    __shared__ int ws[8];
    int tid = threadIdx.x;
    int i = blockIdx.x * 256 + tid;
    int v = (i < n) ? inc[i] : 0;
    int incl = block_incl_scan(v, tid, ws);
    if (tid == 255) bsums[blockIdx.x] = incl;
}

__global__ __launch_bounds__(256)
void k_scan3(const int* __restrict__ inc, int n, int nb, int E,
             const int* __restrict__ bsums, int* __restrict__ rowp,
             int* __restrict__ cur, float* __restrict__ iq) {
    __shared__ int ws[8];
    __shared__ int soff[256];
    int tid = threadIdx.x;

    int vb = (tid < nb) ? bsums[tid] : 0;
    int inclb = block_incl_scan(vb, tid, ws);
    soff[tid] = inclb - vb;
    __syncthreads();
    int blockoff = soff[blockIdx.x];
    __syncthreads();

    int i = blockIdx.x * 256 + tid;
    int v = (i < n) ? inc[i] : 0;
    int incl = block_incl_scan(v, tid, ws);
    if (i < n) {
        int ex = incl - v + blockoff;
        rowp[i] = ex;
        cur[i] = ex;
        iq[i] = rsqrtf((float)max(v, 1));
    }
    if (blockIdx.x == 0 && tid == 0) rowp[n] = E;
}

// ---------------- CSR fill -----------------------------------------------------
__global__ void k_fill(const int* __restrict__ ei, int E,
                       int* __restrict__ cur, int* __restrict__ csr) {
    int e = blockIdx.x * blockDim.x + threadIdx.x;
    if (e < E) {
        int d = ei[E + e];
        int pos = atomicAdd(&cur[d], 1);
        csr[pos] = ei[e];
    }
}

// ---------------- MMA helper ----------------------------------------------------
__device__ __forceinline__ void mma16816(float* c, const unsigned* a,
                                         unsigned b0, unsigned b1) {
    asm volatile(
        "mma.sync.aligned.m16n8k16.row.col.f32.f16.f16.f32 "
        "{%0,%1,%2,%3}, {%4,%5,%6,%7}, {%8,%9}, {%0,%1,%2,%3};"
        : "+f"(c[0]), "+f"(c[1]), "+f"(c[2]), "+f"(c[3])
        : "r"(a[0]), "r"(a[1]), "r"(a[2]), "r"(a[3]), "r"(b0), "r"(b1));
}

#define LDA 136   // padded smem stride in halves

// ---------------- common MMA phase ---------------------------------------------
__device__ __forceinline__ void mma_phase(
    const __half* As, const __half* Bh, const __half* Bl,
    __half* __restrict__ Cm, int rowBase, int nrows,
    int wr, int wc, int g, int tg) {
    float acc[2][8][4];
#pragma unroll
    for (int mt = 0; mt < 2; mt++)
#pragma unroll
        for (int nt = 0; nt < 8; nt++)
#pragma unroll
            for (int q = 0; q < 4; q++) acc[mt][nt][q] = 0.0f;

#pragma unroll
    for (int ks = 0; ks < 8; ks++) {
        const int k0 = ks * 16;
        unsigned a[2][4];
#pragma unroll
        for (int mt = 0; mt < 2; mt++) {
            const __half* pr = As + (wr * 32 + mt * 16 + g) * LDA + k0 + tg * 2;
            a[mt][0] = *(const unsigned*)(pr);
            a[mt][1] = *(const unsigned*)(pr + 8 * LDA);
            a[mt][2] = *(const unsigned*)(pr + 8);
            a[mt][3] = *(const unsigned*)(pr + 8 * LDA + 8);
        }
#pragma unroll
        for (int nt = 0; nt < 8; nt++) {
            const int n = wc * 64 + nt * 8 + g;
            const __half* ph = Bh + n * LDA + k0 + tg * 2;
            const __half* pl = Bl + n * LDA + k0 + tg * 2;
            unsigned bh0 = *(const unsigned*)(ph);
            unsigned bh1 = *(const unsigned*)(ph + 8);
            unsigned bl0 = *(const unsigned*)(pl);
            unsigned bl1 = *(const unsigned*)(pl + 8);
#pragma unroll
            for (int mt = 0; mt < 2; mt++) {
                mma16816(acc[mt][nt], a[mt], bh0, bh1);
                mma16816(acc[mt][nt], a[mt], bl0, bl1);
            }
        }
    }

#pragma unroll
    for (int mt = 0; mt < 2; mt++) {
        int r0 = rowBase + wr * 32 + mt * 16 + g;
        int r1 = r0 + 8;
#pragma unroll
        for (int nt = 0; nt < 8; nt++) {
            int col = wc * 64 + nt * 8 + tg * 2;
            if (r0 < nrows)
                *(__half2*)(Cm + (size_t)r0 * D + col) =
                    __floats2half2_rn(acc[mt][nt][0], acc[mt][nt][1]);
            if (r1 < nrows)
                *(__half2*)(Cm + (size_t)r1 * D + col) =
                    __floats2half2_rn(acc[mt][nt][2], acc[mt][nt][3]);
        }
    }
}

// ---------------- layer-1 GEMM: fp32 A scaled by rsqrt(outdeg) inline ----------
__global__ __launch_bounds__(256)
void k_gemm_tc(const float* __restrict__ A, const int* __restrict__ outc,
               const __half* __restrict__ Whi, const __half* __restrict__ Wlo,
               __half* __restrict__ Cm, int nrows, int ntiles) {
    extern __shared__ __half sm[];
    __half* As = sm;
    __half* Bh = sm + 128 * LDA;
    __half* Bl = Bh + 128 * LDA;

    const int tid = threadIdx.x;
    const int wid = tid >> 5, lane = tid & 31;
    const int wr = wid >> 1, wc = wid & 1;
    const int g = lane >> 2, tg = lane & 3;

    for (int j = tid; j < 2048; j += 256) {
        int n = j >> 4, kc = (j & 15) * 8;
        *(uint4*)(Bh + n * LDA + kc) = *(const uint4*)(Whi + n * D + kc);
        *(uint4*)(Bl + n * LDA + kc) = *(const uint4*)(Wlo + n * D + kc);
    }

    for (int tile = blockIdx.x; tile < ntiles; tile += gridDim.x) {
        const int rowBase = tile * 128;
        __syncthreads();
        for (int j = tid; j < 4096; j += 256) {
            int r = j >> 5, kc = (j & 31) * 4;
            int gr = rowBase + r;
            __half2 o[2];
            if (gr < nrows) {
                float s = rsqrtf((float)max(outc[gr], 1));
                float4 v = *(const float4*)(A + (size_t)gr * D + kc);
                o[0] = __floats2half2_rn(v.x * s, v.y * s);
                o[1] = __floats2half2_rn(v.z * s, v.w * s);
            } else {
                o[0] = __half2half2(__float2half(0.f));
                o[1] = o[0];
            }
            *(uint2*)(As + r * LDA + kc) = *(uint2*)o;
        }
        __syncthreads();
        mma_phase(As, Bh, Bl, Cm, rowBase, nrows, wr, wc, g, tg);
    }
}

// ---------------- layer-2 GEMM: fp16 A straight copy ---------------------------
__global__ __launch_bounds__(256)
void k_gemm_tc16(const __half* __restrict__ A,
                 const __half* __restrict__ Whi, const __half* __restrict__ Wlo,
                 __half* __restrict__ Cm, int nrows, int ntiles) {
    extern __shared__ __half sm[];
    __half* As = sm;
    __half* Bh = sm + 128 * LDA;
    __half* Bl = Bh + 128 * LDA;

    const int tid = threadIdx.x;
    const int wid = tid >> 5, lane = tid & 31;
    const int wr = wid >> 1, wc = wid & 1;
    const int g = lane >> 2, tg = lane & 3;

    for (int j = tid; j < 2048; j += 256) {
        int n = j >> 4, kc = (j & 15) * 8;
        *(uint4*)(Bh + n * LDA + kc) = *(const uint4*)(Whi + n * D + kc);
        *(uint4*)(Bl + n * LDA + kc) = *(const uint4*)(Wlo + n * D + kc);
    }

    for (int tile = blockIdx.x; tile < ntiles; tile += gridDim.x) {
        const int rowBase = tile * 128;
        __syncthreads();
        for (int j = tid; j < 2048; j += 256) {
            int r = j >> 4, kc = (j & 15) * 8;
            int gr = rowBase + r;
            uint4 v = make_uint4(0u, 0u, 0u, 0u);
            if (gr < nrows) v = *(const uint4*)(A + (size_t)gr * D + kc);
            *(uint4*)(As + r * LDA + kc) = v;
        }
        __syncthreads();
        mma_phase(As, Bh, Bl, Cm, rowBase, nrows, wr, wc, g, tg);
    }
}

// ---------------- gather accumulate helpers -------------------------------------
__device__ __forceinline__ void acc_uint2(float4& acc, uint2 r) {
    float2 a = __half22float2(*(__half2*)&r.x);
    float2 b = __half22float2(*(__half2*)&r.y);
    acc.x += a.x; acc.y += a.y; acc.z += b.x; acc.w += b.y;
}

// ---------------- gather + fused epilogue (+ optional pooling + final head) ----
// SCALE_OQ: multiply by rsqrt(outdeg) (feeds next GEMM).
// DO_POOL: accumulate into g_sums; last block computes the classifier head.
template <int SCALE_OQ, int DO_POOL>
__global__ __launch_bounds__(256)
void k_gather(const int* __restrict__ csr, const int* __restrict__ rowp,
              const __half* __restrict__ A, const float* __restrict__ isq,
              const float* __restrict__ b, const int* __restrict__ outc,
              __half* __restrict__ out, int n, const int* __restrict__ n2g,
              const float* __restrict__ Wl, const float* __restrict__ bl,
              float* __restrict__ fout) {
    __shared__ float sacc[DO_POOL ? G * D : 1];
    __shared__ int slast[DO_POOL ? 1 : 1];
    if (DO_POOL) {
        for (int j = threadIdx.x; j < G * D; j += 256) sacc[j] = 0.0f;
        __syncthreads();
    }

    int w = (blockIdx.x * blockDim.x + threadIdx.x) >> 5;
    int lane = threadIdx.x & 31;
    int col = lane * 4;
    const unsigned FULL = 0xffffffffu;

    if (w < n) {
        int s0 = rowp[w], s1 = rowp[w + 1];
        float4 acc = make_float4(0.f, 0.f, 0.f, 0.f);

        for (int base = s0; base < s1; base += 32) {
            int cnt = min(32, s1 - base);
            int myidx = (lane < cnt) ? csr[base + lane] : 0;
            int t = 0;
            for (; t + 16 <= cnt; t += 16) {
                uint2 r[16];
#pragma unroll
                for (int u = 0; u < 16; u++) {
                    int s = __shfl_sync(FULL, myidx, t + u);
                    r[u] = *(const uint2*)(A + (size_t)s * D + col);
                }
#pragma unroll
                for (int u = 0; u < 16; u++) acc_uint2(acc, r[u]);
            }
            for (; t + 8 <= cnt; t += 8) {
                uint2 r[8];
#pragma unroll
                for (int u = 0; u < 8; u++) {
                    int s = __shfl_sync(FULL, myidx, t + u);
                    r[u] = *(const uint2*)(A + (size_t)s * D + col);
                }
#pragma unroll
                for (int u = 0; u < 8; u++) acc_uint2(acc, r[u]);
            }
            for (; t + 4 <= cnt; t += 4) {
                uint2 r[4];
#pragma unroll
                for (int u = 0; u < 4; u++) {
                    int s = __shfl_sync(FULL, myidx, t + u);
                    r[u] = *(const uint2*)(A + (size_t)s * D + col);
                }
#pragma unroll
                for (int u = 0; u < 4; u++) acc_uint2(acc, r[u]);
            }
            for (; t < cnt; t++) {
                int s = __shfl_sync(FULL, myidx, t);
                acc_uint2(acc, *(const uint2*)(A + (size_t)s * D + col));
            }
        }

        float sc = isq[w];
        float post = SCALE_OQ ? rsqrtf((float)max(outc[w], 1)) : 1.0f;
        float4 bb = *(const float4*)(b + col);
        float2 q0, q1;
        q0.x = fmaxf(fmaf(acc.x, sc, bb.x), 0.0f) * post;
        q0.y = fmaxf(fmaf(acc.y, sc, bb.y), 0.0f) * post;
        q1.x = fmaxf(fmaf(acc.z, sc, bb.z), 0.0f) * post;
        q1.y = fmaxf(fmaf(acc.w, sc, bb.w), 0.0f) * post;

        if (!DO_POOL) {
            __half2 o[2] = {__float22half2_rn(q0), __float22half2_rn(q1)};
            *(uint2*)(out + (size_t)w * D + col) = *(uint2*)o;
        } else {
            int gidx = n2g[w] * D + col;
            atomicAdd(&sacc[gidx + 0], q0.x);
            atomicAdd(&sacc[gidx + 1], q0.y);
            atomicAdd(&sacc[gidx + 2], q1.x);
            atomicAdd(&sacc[gidx + 3], q1.y);
        }
    }

    if (DO_POOL) {
        __syncthreads();
        for (int j = threadIdx.x; j < G * D; j += 256) {
            float v = sacc[j];
            if (v != 0.0f) atomicAdd(&g_sums[j], v);
        }
        // last block computes the classifier head
        __threadfence();
        if (threadIdx.x == 0)
            slast[0] = (atomicAdd(&g_done, 1) == (int)gridDim.x - 1) ? 1 : 0;
        __syncthreads();
        if (slast[0]) {
            __threadfence();
            __shared__ float logits[G * C];
            __shared__ float scnt[G];
            int tid = threadIdx.x;
            if (tid < G) {
                int lo = 0, hi = n;
                while (lo < hi) { int m = (lo + hi) >> 1; if (n2g[m] < tid) lo = m + 1; else hi = m; }
                int lo2 = lo, hi2 = n;
                while (lo2 < hi2) { int m = (lo2 + hi2) >> 1; if (n2g[m] < tid + 1) lo2 = m + 1; else hi2 = m; }
                scnt[tid] = fmaxf((float)(lo2 - lo), 1.0f);
            }
            __syncthreads();
            if (tid < 128) {
#pragma unroll
                for (int g = 0; g < G; g++)
                    sacc[g * D + tid] = g_sums[g * D + tid] / scnt[g];
            }
            __syncthreads();
            if (tid < G * C) {
                int g = tid / C, c = tid % C;
                float acc = bl[c];
                for (int k = 0; k < D; k++)
                    acc = fmaf(sacc[g * D + k], Wl[k * C + c], acc);
                logits[tid] = acc;
            }
            __syncthreads();
            if (tid < G) {
                float m = -1e30f;
                for (int c = 0; c < C; c++) m = fmaxf(m, logits[tid * C + c]);
                float s = 0.0f;
                float e[C];
                for (int c = 0; c < C; c++) { e[c] = expf(logits[tid * C + c] - m); s += e[c]; }
                float inv = 1.0f / s;
                for (int c = 0; c < C; c++) fout[tid * C + c] = e[c] * inv;
            }
        }
    }
}

// ---------------- launch --------------------------------------------------------
extern "C" void kernel_launch(void* const* d_in, const int* in_sizes, int n_in,
                              void* d_out, int out_size) {
    const float* x   = (const float*)d_in[0];
    const int*   ei  = (const int*)d_in[1];
    const int*   n2g = (const int*)d_in[2];
    const float* W1  = (const float*)d_in[3];
    const float* b1  = (const float*)d_in[4];
    const float* W2  = (const float*)d_in[5];
    const float* b2  = (const float*)d_in[6];
    const float* Wl  = (const float*)d_in[7];
    const float* bl  = (const float*)d_in[8];
    float* out = (float*)d_out;

    const int N = in_sizes[2];
    const int E = in_sizes[1] / 2;

    float* inq  = nullptr; cudaGetSymbolAddress((void**)&inq,  g_in_isqrt);
    __half* hA  = nullptr; cudaGetSymbolAddress((void**)&hA, g_h16A);
    __half* hB  = nullptr; cudaGetSymbolAddress((void**)&hB, g_h16B);
    __half* w1h = nullptr; cudaGetSymbolAddress((void**)&w1h, g_W1hi);
    __half* w1l = nullptr; cudaGetSymbolAddress((void**)&w1l, g_W1lo);
    __half* w2h = nullptr; cudaGetSymbolAddress((void**)&w2h, g_W2hi);
    __half* w2l = nullptr; cudaGetSymbolAddress((void**)&w2l, g_W2lo);
    float* sums = nullptr; cudaGetSymbolAddress((void**)&sums, g_sums);
    int* outc = nullptr; cudaGetSymbolAddress((void**)&outc, g_outcnt);
    int* inc  = nullptr; cudaGetSymbolAddress((void**)&inc,  g_incnt);
    int* rowp = nullptr; cudaGetSymbolAddress((void**)&rowp, g_rowptr);
    int* cur  = nullptr; cudaGetSymbolAddress((void**)&cur,  g_cursor);
    int* csr  = nullptr; cudaGetSymbolAddress((void**)&csr,  g_csr);
    int* bsum = nullptr; cudaGetSymbolAddress((void**)&bsum, g_bsums);

    const int nb = (N + 255) / 256;
    const int ntiles = (N + 127) / 128;
    const int gemmBlocks = 296;
    const int gatherBlocks = (N * 32 + 255) / 256;
    const int smemGemm = 3 * 128 * LDA * (int)sizeof(__half);

    static cudaStream_t s1;
    static cudaEvent_t ev_fork, ev_csr;
    static int s_init = 0;
    if (!s_init) {
        cudaFuncSetAttribute(k_gemm_tc,
                             cudaFuncAttributeMaxDynamicSharedMemorySize, smemGemm);
        cudaFuncSetAttribute(k_gemm_tc16,
                             cudaFuncAttributeMaxDynamicSharedMemorySize, smemGemm);
        cudaStreamCreateWithFlags(&s1, cudaStreamNonBlocking);
        cudaEventCreateWithFlags(&ev_fork, cudaEventDisableTiming);
        cudaEventCreateWithFlags(&ev_csr, cudaEventDisableTiming);
        s_init = 1;
    }

    // 0..1: setup, degrees (main)
    k_setup<<<nb, 256>>>(outc, inc, N, sums, W1, W2, w1h, w1l, w2h, w2l);
    k_degcount<<<(E + 255) / 256, 256>>>(ei, E, outc, inc);

    // fork: CSR build on s1; layer-1 GEMM on main (needs only outc)
    cudaEventRecord(ev_fork, 0);
    cudaStreamWaitEvent(s1, ev_fork, 0);

    k_scan1<<<nb, 256, 0, s1>>>(inc, N, bsum);
    k_scan3<<<nb, 256, 0, s1>>>(inc, N, nb, E, bsum, rowp, cur, inq);
    k_fill<<<(E + 255) / 256, 256, 0, s1>>>(ei, E, cur, csr);

    k_gemm_tc<<<gemmBlocks, 256, smemGemm>>>(x, outc, w1h, w1l, hA, N, ntiles);

    cudaEventRecord(ev_csr, s1);
    cudaStreamWaitEvent(0, ev_csr, 0);

    // gather1 (folds oq), gemm2, gather2 + fused pool + fused head
    k_gather<1, 0><<<gatherBlocks, 256>>>(csr, rowp, hA, inq, b1, outc, hB, N,
                                          n2g, Wl, bl, out);
    k_gemm_tc16<<<gemmBlocks, 256, smemGemm>>>(hB, w2h, w2l, hA, N, ntiles);
    k_gather<0, 1><<<gatherBlocks, 256>>>(csr, rowp, hA, inq, b2, outc, hB, N,
                                          n2g, Wl, bl, out);
}

// round 13
// speedup vs baseline: 1.1364x; 1.1364x over previous
#include <cuda_runtime.h>
#include <cuda_fp16.h>
#include <cuda_fp8.h>

#define NN 50000
#define EE 800000
#define D  128
#define G  8
#define C  10

// ---------------- scratch (static device globals; no allocs allowed) --------
__device__ float         g_in_isqrt[NN];
__device__ unsigned char g_h8A[NN * D];
__device__ unsigned char g_h8B[NN * D];
__device__ __half        g_W1hi[D * D];
__device__ __half        g_W1lo[D * D];
__device__ __half        g_W2hi[D * D];
__device__ __half        g_W2lo[D * D];
__device__ float         g_sums[G * D];
__device__ int           g_outcnt[NN];
__device__ int           g_incnt[NN];
__device__ int           g_rowptr[NN + 1];
__device__ int           g_cursor[NN];
__device__ int           g_csr[EE];
__device__ int           g_bsums[256];

// ---------------- fp8 helpers ---------------------------------------------------
__device__ __forceinline__ unsigned short pack_fp8x2(float a, float b) {
    float2 f = make_float2(a, b);
    return __nv_cvt_float2_to_fp8x2(f, __NV_SATFINITE, __NV_E4M3);
}
__device__ __forceinline__ float2 unpack_fp8x2(unsigned v) {
    __half2_raw hr = __nv_cvt_fp8x2_to_halfraw2((__nv_fp8x2_storage_t)v, __NV_E4M3);
    return __half22float2(*(__half2*)&hr);
}
__device__ __forceinline__ __half2 fp8x2_to_h2(unsigned v) {
    __half2_raw hr = __nv_cvt_fp8x2_to_halfraw2((__nv_fp8x2_storage_t)v, __NV_E4M3);
    return *(__half2*)&hr;
}

// ---------------- setup: zero degree arrays + pool sums, convert weights ------
__global__ __launch_bounds__(256)
void k_setup(int* __restrict__ outc, int* __restrict__ inc, int n,
             float* __restrict__ sums,
             const float* __restrict__ W1, const float* __restrict__ W2,
             __half* __restrict__ w1h, __half* __restrict__ w1l,
             __half* __restrict__ w2h, __half* __restrict__ w2l) {
    int i = blockIdx.x * 256 + threadIdx.x;
    if (i < n) { outc[i] = 0; inc[i] = 0; }
    if (i < G * D) sums[i] = 0.0f;
    if (i < D * D) {
        int k = i >> 7, nn = i & 127;
        float v = W1[i];
        __half hi = __float2half_rn(v);
        w1h[nn * D + k] = hi;
        w1l[nn * D + k] = __float2half_rn(v - __half2float(hi));
        v = W2[i];
        hi = __float2half_rn(v);
        w2h[nn * D + k] = hi;
        w2l[nn * D + k] = __float2half_rn(v - __half2float(hi));
    }
}

// ---------------- degree histograms (int) ------------------------------------
__global__ void k_degcount(const int* __restrict__ ei, int E,
                           int* __restrict__ outc, int* __restrict__ inc) {
    int e = blockIdx.x * blockDim.x + threadIdx.x;
    if (e < E) {
        atomicAdd(&outc[ei[e]], 1);
        atomicAdd(&inc[ei[E + e]], 1);
    }
}

// ---------------- scan helpers -------------------------------------------------
__device__ __forceinline__ int warp_incl_scan(int v, int lane) {
#pragma unroll
    for (int o = 1; o < 32; o <<= 1) {
        int t = __shfl_up_sync(0xffffffffu, v, o);
        if (lane >= o) v += t;
    }
    return v;
}

__device__ __forceinline__ int block_incl_scan(int v, int tid, int* ws) {
    int lane = tid & 31, wid = tid >> 5;
    int s = warp_incl_scan(v, lane);
    if (lane == 31) ws[wid] = s;
    __syncthreads();
    if (wid == 0) {
        int t = (lane < 8) ? ws[lane] : 0;
        t = warp_incl_scan(t, lane);
        if (lane < 8) ws[lane] = t;
    }
    __syncthreads();
    return s + (wid > 0 ? ws[wid - 1] : 0);
}

__global__ __launch_bounds__(256)
void k_scan1(const int* __restrict__ inc, int n, int* __restrict__ bsums) {
    __shared__ int ws[8];
    int tid = threadIdx.x;
    int i = blockIdx.x * 256 + tid;
    int v = (i < n) ? inc[i] : 0;
    int incl = block_incl_scan(v, tid, ws);
    if (tid == 255) bsums[blockIdx.x] = incl;
}

__global__ __launch_bounds__(256)
void k_scan3(const int* __restrict__ inc, int n, int nb, int E,
             const int* __restrict__ bsums, int* __restrict__ rowp,
             int* __restrict__ cur, float* __restrict__ iq) {
    __shared__ int ws[8];
    __shared__ int soff[256];
    int tid = threadIdx.x;

    int vb = (tid < nb) ? bsums[tid] : 0;
    int inclb = block_incl_scan(vb, tid, ws);
    soff[tid] = inclb - vb;
    __syncthreads();
    int blockoff = soff[blockIdx.x];
    __syncthreads();

    int i = blockIdx.x * 256 + tid;
    int v = (i < n) ? inc[i] : 0;
    int incl = block_incl_scan(v, tid, ws);
    if (i < n) {
        int ex = incl - v + blockoff;
        rowp[i] = ex;
        cur[i] = ex;
        iq[i] = rsqrtf((float)max(v, 1));
    }
    if (blockIdx.x == 0 && tid == 0) rowp[n] = E;
}

// ---------------- CSR fill -----------------------------------------------------
__global__ void k_fill(const int* __restrict__ ei, int E,
                       int* __restrict__ cur, int* __restrict__ csr) {
    int e = blockIdx.x * blockDim.x + threadIdx.x;
    if (e < E) {
        int d = ei[E + e];
        int pos = atomicAdd(&cur[d], 1);
        csr[pos] = ei[e];
    }
}

// ---------------- MMA helper ----------------------------------------------------
__device__ __forceinline__ void mma16816(float* c, const unsigned* a,
                                         unsigned b0, unsigned b1) {
    asm volatile(
        "mma.sync.aligned.m16n8k16.row.col.f32.f16.f16.f32 "
        "{%0,%1,%2,%3}, {%4,%5,%6,%7}, {%8,%9}, {%0,%1,%2,%3};"
        : "+f"(c[0]), "+f"(c[1]), "+f"(c[2]), "+f"(c[3])
        : "r"(a[0]), "r"(a[1]), "r"(a[2]), "r"(a[3]), "r"(b0), "r"(b1));
}

#define LDA 136   // padded smem stride in halves

// ---------------- common MMA phase (fp8 output) ---------------------------------
__device__ __forceinline__ void mma_phase(
    const __half* As, const __half* Bh, const __half* Bl,
    unsigned char* __restrict__ Cm, int rowBase, int nrows,
    int wr, int wc, int g, int tg) {
    float acc[2][8][4];
#pragma unroll
    for (int mt = 0; mt < 2; mt++)
#pragma unroll
        for (int nt = 0; nt < 8; nt++)
#pragma unroll
            for (int q = 0; q < 4; q++) acc[mt][nt][q] = 0.0f;

#pragma unroll
    for (int ks = 0; ks < 8; ks++) {
        const int k0 = ks * 16;
        unsigned a[2][4];
#pragma unroll
        for (int mt = 0; mt < 2; mt++) {
            const __half* pr = As + (wr * 32 + mt * 16 + g) * LDA + k0 + tg * 2;
            a[mt][0] = *(const unsigned*)(pr);
            a[mt][1] = *(const unsigned*)(pr + 8 * LDA);
            a[mt][2] = *(const unsigned*)(pr + 8);
            a[mt][3] = *(const unsigned*)(pr + 8 * LDA + 8);
        }
#pragma unroll
        for (int nt = 0; nt < 8; nt++) {
            const int n = wc * 64 + nt * 8 + g;
            const __half* ph = Bh + n * LDA + k0 + tg * 2;
            const __half* pl = Bl + n * LDA + k0 + tg * 2;
            unsigned bh0 = *(const unsigned*)(ph);
            unsigned bh1 = *(const unsigned*)(ph + 8);
            unsigned bl0 = *(const unsigned*)(pl);
            unsigned bl1 = *(const unsigned*)(pl + 8);
#pragma unroll
            for (int mt = 0; mt < 2; mt++) {
                mma16816(acc[mt][nt], a[mt], bh0, bh1);
                mma16816(acc[mt][nt], a[mt], bl0, bl1);
            }
        }
    }

#pragma unroll
    for (int mt = 0; mt < 2; mt++) {
        int r0 = rowBase + wr * 32 + mt * 16 + g;
        int r1 = r0 + 8;
#pragma unroll
        for (int nt = 0; nt < 8; nt++) {
            int col = wc * 64 + nt * 8 + tg * 2;
            if (r0 < nrows)
                *(unsigned short*)(Cm + (size_t)r0 * D + col) =
                    pack_fp8x2(acc[mt][nt][0], acc[mt][nt][1]);
            if (r1 < nrows)
                *(unsigned short*)(Cm + (size_t)r1 * D + col) =
                    pack_fp8x2(acc[mt][nt][2], acc[mt][nt][3]);
        }
    }
}

// ---------------- layer-1 GEMM: fp32 A scaled by rsqrt(outdeg), fp8 out --------
__global__ __launch_bounds__(256)
void k_gemm_tc(const float* __restrict__ A, const int* __restrict__ outc,
               const __half* __restrict__ Whi, const __half* __restrict__ Wlo,
               unsigned char* __restrict__ Cm, int nrows, int ntiles) {
    extern __shared__ __half sm[];
    __half* As = sm;
    __half* Bh = sm + 128 * LDA;
    __half* Bl = Bh + 128 * LDA;

    const int tid = threadIdx.x;
    const int wid = tid >> 5, lane = tid & 31;
    const int wr = wid >> 1, wc = wid & 1;
    const int g = lane >> 2, tg = lane & 3;

    for (int j = tid; j < 2048; j += 256) {
        int n = j >> 4, kc = (j & 15) * 8;
        *(uint4*)(Bh + n * LDA + kc) = *(const uint4*)(Whi + n * D + kc);
        *(uint4*)(Bl + n * LDA + kc) = *(const uint4*)(Wlo + n * D + kc);
    }

    for (int tile = blockIdx.x; tile < ntiles; tile += gridDim.x) {
        const int rowBase = tile * 128;
        __syncthreads();
        for (int j = tid; j < 4096; j += 256) {
            int r = j >> 5, kc = (j & 31) * 4;
            int gr = rowBase + r;
            __half2 o[2];
            if (gr < nrows) {
                float s = rsqrtf((float)max(outc[gr], 1));
                float4 v = *(const float4*)(A + (size_t)gr * D + kc);
                o[0] = __floats2half2_rn(v.x * s, v.y * s);
                o[1] = __floats2half2_rn(v.z * s, v.w * s);
            } else {
                o[0] = __half2half2(__float2half(0.f));
                o[1] = o[0];
            }
            *(uint2*)(As + r * LDA + kc) = *(uint2*)o;
        }
        __syncthreads();
        mma_phase(As, Bh, Bl, Cm, rowBase, nrows, wr, wc, g, tg);
    }
}

// ---------------- layer-2 GEMM: fp8 A converted in smem load, fp8 out ----------
__global__ __launch_bounds__(256)
void k_gemm_tc8(const unsigned char* __restrict__ A,
                const __half* __restrict__ Whi, const __half* __restrict__ Wlo,
                unsigned char* __restrict__ Cm, int nrows, int ntiles) {
    extern __shared__ __half sm[];
    __half* As = sm;
    __half* Bh = sm + 128 * LDA;
    __half* Bl = Bh + 128 * LDA;

    const int tid = threadIdx.x;
    const int wid = tid >> 5, lane = tid & 31;
    const int wr = wid >> 1, wc = wid & 1;
    const int g = lane >> 2, tg = lane & 3;

    for (int j = tid; j < 2048; j += 256) {
        int n = j >> 4, kc = (j & 15) * 8;
        *(uint4*)(Bh + n * LDA + kc) = *(const uint4*)(Whi + n * D + kc);
        *(uint4*)(Bl + n * LDA + kc) = *(const uint4*)(Wlo + n * D + kc);
    }

    for (int tile = blockIdx.x; tile < ntiles; tile += gridDim.x) {
        const int rowBase = tile * 128;
        __syncthreads();
        for (int j = tid; j < 2048; j += 256) {
            int r = j >> 4, kc = (j & 15) * 8;
            int gr = rowBase + r;
            __half2 h[4];
            if (gr < nrows) {
                uint2 raw = *(const uint2*)(A + (size_t)gr * D + kc);
                h[0] = fp8x2_to_h2(raw.x & 0xffffu);
                h[1] = fp8x2_to_h2(raw.x >> 16);
                h[2] = fp8x2_to_h2(raw.y & 0xffffu);
                h[3] = fp8x2_to_h2(raw.y >> 16);
            } else {
                h[0] = __half2half2(__float2half(0.f));
                h[1] = h[0]; h[2] = h[0]; h[3] = h[0];
            }
            *(uint4*)(As + r * LDA + kc) = *(uint4*)h;
        }
        __syncthreads();
        mma_phase(As, Bh, Bl, Cm, rowBase, nrows, wr, wc, g, tg);
    }
}

// ---------------- gather accumulate helper --------------------------------------
__device__ __forceinline__ void acc_fp8x4(float4& acc, unsigned r) {
    float2 lo = unpack_fp8x2(r & 0xffffu);
    float2 hi = unpack_fp8x2(r >> 16);
    acc.x += lo.x; acc.y += lo.y; acc.z += hi.x; acc.w += hi.y;
}

// ---------------- gather + fused epilogue (+ optional fused pooling) ----------
// SCALE_OQ: multiply by rsqrt(outdeg) (feeds next GEMM).
// DO_POOL: accumulate into g_sums, skip the global store entirely.
template <int SCALE_OQ, int DO_POOL>
__global__ __launch_bounds__(256)
void k_gather(const int* __restrict__ csr, const int* __restrict__ rowp,
              const unsigned char* __restrict__ A, const float* __restrict__ isq,
              const float* __restrict__ b, const int* __restrict__ outc,
              unsigned char* __restrict__ out, int n, const int* __restrict__ n2g) {
    __shared__ float sacc[DO_POOL ? G * D : 1];
    if (DO_POOL) {
        for (int j = threadIdx.x; j < G * D; j += 256) sacc[j] = 0.0f;
        __syncthreads();
    }

    int w = (blockIdx.x * blockDim.x + threadIdx.x) >> 5;
    int lane = threadIdx.x & 31;
    int col = lane * 4;
    const unsigned FULL = 0xffffffffu;

    if (w < n) {
        int s0 = rowp[w], s1 = rowp[w + 1];
        float4 acc = make_float4(0.f, 0.f, 0.f, 0.f);

        for (int base = s0; base < s1; base += 32) {
            int cnt = min(32, s1 - base);
            int myidx = (lane < cnt) ? csr[base + lane] : 0;
            int t = 0;
            for (; t + 8 <= cnt; t += 8) {
                unsigned r[8];
#pragma unroll
                for (int u = 0; u < 8; u++) {
                    int s = __shfl_sync(FULL, myidx, t + u);
                    r[u] = *(const unsigned*)(A + (size_t)s * D + col);
                }
#pragma unroll
                for (int u = 0; u < 8; u++) acc_fp8x4(acc, r[u]);
            }
            for (; t < cnt; t++) {
                int s = __shfl_sync(FULL, myidx, t);
                acc_fp8x4(acc, *(const unsigned*)(A + (size_t)s * D + col));
            }
        }

        float sc = isq[w];
        float post = SCALE_OQ ? rsqrtf((float)max(outc[w], 1)) : 1.0f;
        float4 bb = *(const float4*)(b + col);
        float q0 = fmaxf(fmaf(acc.x, sc, bb.x), 0.0f) * post;
        float q1 = fmaxf(fmaf(acc.y, sc, bb.y), 0.0f) * post;
        float q2 = fmaxf(fmaf(acc.z, sc, bb.z), 0.0f) * post;
        float q3 = fmaxf(fmaf(acc.w, sc, bb.w), 0.0f) * post;

        if (!DO_POOL) {
            unsigned o = (unsigned)pack_fp8x2(q0, q1) |
                         ((unsigned)pack_fp8x2(q2, q3) << 16);
            *(unsigned*)(out + (size_t)w * D + col) = o;
        } else {
            int gidx = n2g[w] * D + col;
            atomicAdd(&sacc[gidx + 0], q0);
            atomicAdd(&sacc[gidx + 1], q1);
            atomicAdd(&sacc[gidx + 2], q2);
            atomicAdd(&sacc[gidx + 3], q3);
        }
    }

    if (DO_POOL) {
        __syncthreads();
        for (int j = threadIdx.x; j < G * D; j += 256) {
            float v = sacc[j];
            if (v != 0.0f) atomicAdd(&g_sums[j], v);
        }
    }
}

// ---------------- final: counts via binary search, mean -> linear -> softmax --
__global__ __launch_bounds__(128)
void k_final(const float* __restrict__ Wl, const float* __restrict__ bl,
             const int* __restrict__ n2g, int n, float* __restrict__ out) {
    __shared__ float hg[G * D];
    __shared__ float logits[G * C];
    __shared__ float scnt[G];
    int tid = threadIdx.x;
    if (tid < G) {
        int lo = 0, hi = n;
        while (lo < hi) { int m = (lo + hi) >> 1; if (n2g[m] < tid) lo = m + 1; else hi = m; }
        int lo2 = lo, hi2 = n;
        while (lo2 < hi2) { int m = (lo2 + hi2) >> 1; if (n2g[m] < tid + 1) lo2 = m + 1; else hi2 = m; }
        scnt[tid] = fmaxf((float)(lo2 - lo), 1.0f);
    }
    __syncthreads();
#pragma unroll
    for (int g = 0; g < G; g++)
        hg[g * D + tid] = g_sums[g * D + tid] / scnt[g];
    __syncthreads();
    if (tid < G * C) {
        int g = tid / C, c = tid % C;
        float acc = bl[c];
        for (int k = 0; k < D; k++) acc = fmaf(hg[g * D + k], Wl[k * C + c], acc);
        logits[tid] = acc;
    }
    __syncthreads();
    if (tid < G) {
        float m = -1e30f;
        for (int c = 0; c < C; c++) m = fmaxf(m, logits[tid * C + c]);
        float s = 0.0f;
        float e[C];
        for (int c = 0; c < C; c++) { e[c] = expf(logits[tid * C + c] - m); s += e[c]; }
        float inv = 1.0f / s;
        for (int c = 0; c < C; c++) out[tid * C + c] = e[c] * inv;
    }
}

// ---------------- launch --------------------------------------------------------
extern "C" void kernel_launch(void* const* d_in, const int* in_sizes, int n_in,
                              void* d_out, int out_size) {
    const float* x   = (const float*)d_in[0];
    const int*   ei  = (const int*)d_in[1];
    const int*   n2g = (const int*)d_in[2];
    const float* W1  = (const float*)d_in[3];
    const float* b1  = (const float*)d_in[4];
    const float* W2  = (const float*)d_in[5];
    const float* b2  = (const float*)d_in[6];
    const float* Wl  = (const float*)d_in[7];
    const float* bl  = (const float*)d_in[8];
    float* out = (float*)d_out;

    const int N = in_sizes[2];
    const int E = in_sizes[1] / 2;

    float* inq  = nullptr; cudaGetSymbolAddress((void**)&inq,  g_in_isqrt);
    unsigned char* hA = nullptr; cudaGetSymbolAddress((void**)&hA, g_h8A);
    unsigned char* hB = nullptr; cudaGetSymbolAddress((void**)&hB, g_h8B);
    __half* w1h = nullptr; cudaGetSymbolAddress((void**)&w1h, g_W1hi);
    __half* w1l = nullptr; cudaGetSymbolAddress((void**)&w1l, g_W1lo);
    __half* w2h = nullptr; cudaGetSymbolAddress((void**)&w2h, g_W2hi);
    __half* w2l = nullptr; cudaGetSymbolAddress((void**)&w2l, g_W2lo);
    float* sums = nullptr; cudaGetSymbolAddress((void**)&sums, g_sums);
    int* outc = nullptr; cudaGetSymbolAddress((void**)&outc, g_outcnt);
    int* inc  = nullptr; cudaGetSymbolAddress((void**)&inc,  g_incnt);
    int* rowp = nullptr; cudaGetSymbolAddress((void**)&rowp, g_rowptr);
    int* cur  = nullptr; cudaGetSymbolAddress((void**)&cur,  g_cursor);
    int* csr  = nullptr; cudaGetSymbolAddress((void**)&csr,  g_csr);
    int* bsum = nullptr; cudaGetSymbolAddress((void**)&bsum, g_bsums);

    const int nb = (N + 255) / 256;
    const int ntiles = (N + 127) / 128;
    const int gemmBlocks = 296;
    const int gatherBlocks = (N * 32 + 255) / 256;
    const int smemGemm = 3 * 128 * LDA * (int)sizeof(__half);

    static cudaStream_t s1;
    static cudaEvent_t ev_fork, ev_csr;
    static int s_init = 0;
    if (!s_init) {
        cudaFuncSetAttribute(k_gemm_tc,
                             cudaFuncAttributeMaxDynamicSharedMemorySize, smemGemm);
        cudaFuncSetAttribute(k_gemm_tc8,
                             cudaFuncAttributeMaxDynamicSharedMemorySize, smemGemm);
        cudaStreamCreateWithFlags(&s1, cudaStreamNonBlocking);
        cudaEventCreateWithFlags(&ev_fork, cudaEventDisableTiming);
        cudaEventCreateWithFlags(&ev_csr, cudaEventDisableTiming);
        s_init = 1;
    }

    // 0..1: setup, degrees (main)
    k_setup<<<nb, 256>>>(outc, inc, N, sums, W1, W2, w1h, w1l, w2h, w2l);
    k_degcount<<<(E + 255) / 256, 256>>>(ei, E, outc, inc);

    // fork: CSR build on s1; layer-1 GEMM on main (needs only outc)
    cudaEventRecord(ev_fork, 0);
    cudaStreamWaitEvent(s1, ev_fork, 0);

    k_scan1<<<nb, 256, 0, s1>>>(inc, N, bsum);
    k_scan3<<<nb, 256, 0, s1>>>(inc, N, nb, E, bsum, rowp, cur, inq);
    k_fill<<<(E + 255) / 256, 256, 0, s1>>>(ei, E, cur, csr);

    k_gemm_tc<<<gemmBlocks, 256, smemGemm>>>(x, outc, w1h, w1l, hA, N, ntiles);

    cudaEventRecord(ev_csr, s1);
    cudaStreamWaitEvent(0, ev_csr, 0);

    // gather1 (folds oq), gemm2, gather2 + fused pool (no global store)
    k_gather<1, 0><<<gatherBlocks, 256>>>(csr, rowp, hA, inq, b1, outc, hB, N, n2g);
    k_gemm_tc8<<<gemmBlocks, 256, smemGemm>>>(hB, w2h, w2l, hA, N, ntiles);
    k_gather<0, 1><<<gatherBlocks, 256>>>(csr, rowp, hA, inq, b2, outc, hB, N, n2g);

    k_final<<<1, 128>>>(Wl, bl, n2g, N, out);
}

// round 14
// speedup vs baseline: 1.1550x; 1.0163x over previous
#include <cuda_runtime.h>
#include <cuda_fp16.h>
#include <cuda_fp8.h>

#define NN 50000
#define EE 800000
#define D  128
#define G  8
#define C  10

// ---------------- scratch (static device globals; no allocs allowed) --------
__device__ float         g_in_isqrt[NN];
__device__ unsigned char g_h8A[NN * D];
__device__ unsigned char g_h8B[NN * D];
__device__ __half        g_W1hi[D * D];
__device__ __half        g_W1lo[D * D];
__device__ __half        g_W2hi[D * D];
__device__ __half        g_W2lo[D * D];
__device__ float         g_sums[G * D];
__device__ int           g_outcnt[NN];
__device__ int           g_incnt[NN];
__device__ int           g_rowptr[NN + 1];
__device__ int           g_cursor[NN];
__device__ int           g_csr[EE];
__device__ int           g_bsums[256];

// ---------------- fp8 helpers ---------------------------------------------------
__device__ __forceinline__ unsigned short pack_fp8x2(float a, float b) {
    float2 f = make_float2(a, b);
    return __nv_cvt_float2_to_fp8x2(f, __NV_SATFINITE, __NV_E4M3);
}
__device__ __forceinline__ float2 unpack_fp8x2(unsigned v) {
    __half2_raw hr = __nv_cvt_fp8x2_to_halfraw2((__nv_fp8x2_storage_t)v, __NV_E4M3);
    return __half22float2(*(__half2*)&hr);
}
__device__ __forceinline__ __half2 fp8x2_to_h2(unsigned v) {
    __half2_raw hr = __nv_cvt_fp8x2_to_halfraw2((__nv_fp8x2_storage_t)v, __NV_E4M3);
    return *(__half2*)&hr;
}

// ---------------- setup: zero degree arrays + pool sums, convert weights ------
__global__ __launch_bounds__(256)
void k_setup(int* __restrict__ outc, int* __restrict__ inc, int n,
             float* __restrict__ sums,
             const float* __restrict__ W1, const float* __restrict__ W2,
             __half* __restrict__ w1h, __half* __restrict__ w1l,
             __half* __restrict__ w2h, __half* __restrict__ w2l) {
    int i = blockIdx.x * 256 + threadIdx.x;
    if (i < n) { outc[i] = 0; inc[i] = 0; }
    if (i < G * D) sums[i] = 0.0f;
    if (i < D * D) {
        int k = i >> 7, nn = i & 127;
        float v = W1[i];
        __half hi = __float2half_rn(v);
        w1h[nn * D + k] = hi;
        w1l[nn * D + k] = __float2half_rn(v - __half2float(hi));
        v = W2[i];
        hi = __float2half_rn(v);
        w2h[nn * D + k] = hi;
        w2l[nn * D + k] = __float2half_rn(v - __half2float(hi));
    }
}

// ---------------- degree histograms (split: out on main, in on s1) ------------
__global__ void k_degout(const int* __restrict__ ei, int E, int* __restrict__ outc) {
    int e = blockIdx.x * blockDim.x + threadIdx.x;
    if (e < E) atomicAdd(&outc[ei[e]], 1);
}
__global__ void k_degin(const int* __restrict__ ei, int E, int* __restrict__ inc) {
    int e = blockIdx.x * blockDim.x + threadIdx.x;
    if (e < E) atomicAdd(&inc[ei[E + e]], 1);
}

// ---------------- scan helpers -------------------------------------------------
__device__ __forceinline__ int warp_incl_scan(int v, int lane) {
#pragma unroll
    for (int o = 1; o < 32; o <<= 1) {
        int t = __shfl_up_sync(0xffffffffu, v, o);
        if (lane >= o) v += t;
    }
    return v;
}

__device__ __forceinline__ int block_incl_scan(int v, int tid, int* ws) {
    int lane = tid & 31, wid = tid >> 5;
    int s = warp_incl_scan(v, lane);
    if (lane == 31) ws[wid] = s;
    __syncthreads();
    if (wid == 0) {
        int t = (lane < 8) ? ws[lane] : 0;
        t = warp_incl_scan(t, lane);
        if (lane < 8) ws[lane] = t;
    }
    __syncthreads();
    return s + (wid > 0 ? ws[wid - 1] : 0);
}

__global__ __launch_bounds__(256)
void k_scan1(const int* __restrict__ inc, int n, int* __restrict__ bsums) {
    __shared__ int ws[8];
    int tid = threadIdx.x;
    int i = blockIdx.x * 256 + tid;
    int v = (i < n) ? inc[i] : 0;
    int incl = block_incl_scan(v, tid, ws);
    if (tid == 255) bsums[blockIdx.x] = incl;
}

__global__ __launch_bounds__(256)
void k_scan3(const int* __restrict__ inc, int n, int nb, int E,
             const int* __restrict__ bsums, int* __restrict__ rowp,
             int* __restrict__ cur, float* __restrict__ iq) {
    __shared__ int ws[8];
    __shared__ int soff[256];
    int tid = threadIdx.x;

    int vb = (tid < nb) ? bsums[tid] : 0;
    int inclb = block_incl_scan(vb, tid, ws);
    soff[tid] = inclb - vb;
    __syncthreads();
    int blockoff = soff[blockIdx.x];
    __syncthreads();

    int i = blockIdx.x * 256 + tid;
    int v = (i < n) ? inc[i] : 0;
    int incl = block_incl_scan(v, tid, ws);
    if (i < n) {
        int ex = incl - v + blockoff;
        rowp[i] = ex;
        cur[i] = ex;
        iq[i] = rsqrtf((float)max(v, 1));
    }
    if (blockIdx.x == 0 && tid == 0) rowp[n] = E;
}

// ---------------- CSR fill -----------------------------------------------------
__global__ void k_fill(const int* __restrict__ ei, int E,
                       int* __restrict__ cur, int* __restrict__ csr) {
    int e = blockIdx.x * blockDim.x + threadIdx.x;
    if (e < E) {
        int d = ei[E + e];
        int pos = atomicAdd(&cur[d], 1);
        csr[pos] = ei[e];
    }
}

// ---------------- MMA helper ----------------------------------------------------
__device__ __forceinline__ void mma16816(float* c, const unsigned* a,
                                         unsigned b0, unsigned b1) {
    asm volatile(
        "mma.sync.aligned.m16n8k16.row.col.f32.f16.f16.f32 "
        "{%0,%1,%2,%3}, {%4,%5,%6,%7}, {%8,%9}, {%0,%1,%2,%3};"
        : "+f"(c[0]), "+f"(c[1]), "+f"(c[2]), "+f"(c[3])
        : "r"(a[0]), "r"(a[1]), "r"(a[2]), "r"(a[3]), "r"(b0), "r"(b1));
}

#define LDA 136   // padded smem stride in halves

// ---------------- common MMA phase (fp8 output) ---------------------------------
__device__ __forceinline__ void mma_phase(
    const __half* As, const __half* Bh, const __half* Bl,
    unsigned char* __restrict__ Cm, int rowBase, int nrows,
    int wr, int wc, int g, int tg) {
    float acc[2][8][4];
#pragma unroll
    for (int mt = 0; mt < 2; mt++)
#pragma unroll
        for (int nt = 0; nt < 8; nt++)
#pragma unroll
            for (int q = 0; q < 4; q++) acc[mt][nt][q] = 0.0f;

#pragma unroll
    for (int ks = 0; ks < 8; ks++) {
        const int k0 = ks * 16;
        unsigned a[2][4];
#pragma unroll
        for (int mt = 0; mt < 2; mt++) {
            const __half* pr = As + (wr * 32 + mt * 16 + g) * LDA + k0 + tg * 2;
            a[mt][0] = *(const unsigned*)(pr);
            a[mt][1] = *(const unsigned*)(pr + 8 * LDA);
            a[mt][2] = *(const unsigned*)(pr + 8);
            a[mt][3] = *(const unsigned*)(pr + 8 * LDA + 8);
        }
#pragma unroll
        for (int nt = 0; nt < 8; nt++) {
            const int n = wc * 64 + nt * 8 + g;
            const __half* ph = Bh + n * LDA + k0 + tg * 2;
            const __half* pl = Bl + n * LDA + k0 + tg * 2;
            unsigned bh0 = *(const unsigned*)(ph);
            unsigned bh1 = *(const unsigned*)(ph + 8);
            unsigned bl0 = *(const unsigned*)(pl);
            unsigned bl1 = *(const unsigned*)(pl + 8);
#pragma unroll
            for (int mt = 0; mt < 2; mt++) {
                mma16816(acc[mt][nt], a[mt], bh0, bh1);
                mma16816(acc[mt][nt], a[mt], bl0, bl1);
            }
        }
    }

#pragma unroll
    for (int mt = 0; mt < 2; mt++) {
        int r0 = rowBase + wr * 32 + mt * 16 + g;
        int r1 = r0 + 8;
#pragma unroll
        for (int nt = 0; nt < 8; nt++) {
            int col = wc * 64 + nt * 8 + tg * 2;
            if (r0 < nrows)
                *(unsigned short*)(Cm + (size_t)r0 * D + col) =
                    pack_fp8x2(acc[mt][nt][0], acc[mt][nt][1]);
            if (r1 < nrows)
                *(unsigned short*)(Cm + (size_t)r1 * D + col) =
                    pack_fp8x2(acc[mt][nt][2], acc[mt][nt][3]);
        }
    }
}

// ---------------- layer-1 GEMM: fp32 A scaled by rsqrt(outdeg), fp8 out --------
__global__ __launch_bounds__(256)
void k_gemm_tc(const float* __restrict__ A, const int* __restrict__ outc,
               const __half* __restrict__ Whi, const __half* __restrict__ Wlo,
               unsigned char* __restrict__ Cm, int nrows, int ntiles) {
    extern __shared__ __half sm[];
    __half* As = sm;
    __half* Bh = sm + 128 * LDA;
    __half* Bl = Bh + 128 * LDA;

    const int tid = threadIdx.x;
    const int wid = tid >> 5, lane = tid & 31;
    const int wr = wid >> 1, wc = wid & 1;
    const int g = lane >> 2, tg = lane & 3;

    for (int j = tid; j < 2048; j += 256) {
        int n = j >> 4, kc = (j & 15) * 8;
        *(uint4*)(Bh + n * LDA + kc) = *(const uint4*)(Whi + n * D + kc);
        *(uint4*)(Bl + n * LDA + kc) = *(const uint4*)(Wlo + n * D + kc);
    }

    for (int tile = blockIdx.x; tile < ntiles; tile += gridDim.x) {
        const int rowBase = tile * 128;
        __syncthreads();
        for (int j = tid; j < 4096; j += 256) {
            int r = j >> 5, kc = (j & 31) * 4;
            int gr = rowBase + r;
            __half2 o[2];
            if (gr < nrows) {
                float s = rsqrtf((float)max(outc[gr], 1));
                float4 v = *(const float4*)(A + (size_t)gr * D + kc);
                o[0] = __floats2half2_rn(v.x * s, v.y * s);
                o[1] = __floats2half2_rn(v.z * s, v.w * s);
            } else {
                o[0] = __half2half2(__float2half(0.f));
                o[1] = o[0];
            }
            *(uint2*)(As + r * LDA + kc) = *(uint2*)o;
        }
        __syncthreads();
        mma_phase(As, Bh, Bl, Cm, rowBase, nrows, wr, wc, g, tg);
    }
}

// ---------------- layer-2 GEMM: fp8 A converted in smem load, fp8 out ----------
__global__ __launch_bounds__(256)
void k_gemm_tc8(const unsigned char* __restrict__ A,
                const __half* __restrict__ Whi, const __half* __restrict__ Wlo,
                unsigned char* __restrict__ Cm, int nrows, int ntiles) {
    extern __shared__ __half sm[];
    __half* As = sm;
    __half* Bh = sm + 128 * LDA;
    __half* Bl = Bh + 128 * LDA;

    const int tid = threadIdx.x;
    const int wid = tid >> 5, lane = tid & 31;
    const int wr = wid >> 1, wc = wid & 1;
    const int g = lane >> 2, tg = lane & 3;

    for (int j = tid; j < 2048; j += 256) {
        int n = j >> 4, kc = (j & 15) * 8;
        *(uint4*)(Bh + n * LDA + kc) = *(const uint4*)(Whi + n * D + kc);
        *(uint4*)(Bl + n * LDA + kc) = *(const uint4*)(Wlo + n * D + kc);
    }

    for (int tile = blockIdx.x; tile < ntiles; tile += gridDim.x) {
        const int rowBase = tile * 128;
        __syncthreads();
        for (int j = tid; j < 2048; j += 256) {
            int r = j >> 4, kc = (j & 15) * 8;
            int gr = rowBase + r;
            __half2 h[4];
            if (gr < nrows) {
                uint2 raw = *(const uint2*)(A + (size_t)gr * D + kc);
                h[0] = fp8x2_to_h2(raw.x & 0xffffu);
                h[1] = fp8x2_to_h2(raw.x >> 16);
                h[2] = fp8x2_to_h2(raw.y & 0xffffu);
                h[3] = fp8x2_to_h2(raw.y >> 16);
            } else {
                h[0] = __half2half2(__float2half(0.f));
                h[1] = h[0]; h[2] = h[0]; h[3] = h[0];
            }
            *(uint4*)(As + r * LDA + kc) = *(uint4*)h;
        }
        __syncthreads();
        mma_phase(As, Bh, Bl, Cm, rowBase, nrows, wr, wc, g, tg);
    }
}

// ---------------- gather accumulate helper --------------------------------------
__device__ __forceinline__ void acc_fp8x4(float4& acc, unsigned r) {
    float2 lo = unpack_fp8x2(r & 0xffffu);
    float2 hi = unpack_fp8x2(r >> 16);
    acc.x += lo.x; acc.y += lo.y; acc.z += hi.x; acc.w += hi.y;
}

// ---------------- gather + fused epilogue (+ optional fused pooling) ----------
template <int SCALE_OQ, int DO_POOL>
__global__ __launch_bounds__(256)
void k_gather(const int* __restrict__ csr, const int* __restrict__ rowp,
              const unsigned char* __restrict__ A, const float* __restrict__ isq,
              const float* __restrict__ b, const int* __restrict__ outc,
              unsigned char* __restrict__ out, int n, const int* __restrict__ n2g) {
    __shared__ float sacc[DO_POOL ? G * D : 1];
    if (DO_POOL) {
        for (int j = threadIdx.x; j < G * D; j += 256) sacc[j] = 0.0f;
        __syncthreads();
    }

    int w = (blockIdx.x * blockDim.x + threadIdx.x) >> 5;
    int lane = threadIdx.x & 31;
    int col = lane * 4;
    const unsigned FULL = 0xffffffffu;

    if (w < n) {
        int s0 = rowp[w], s1 = rowp[w + 1];
        float4 acc = make_float4(0.f, 0.f, 0.f, 0.f);

        for (int base = s0; base < s1; base += 32) {
            int cnt = min(32, s1 - base);
            int myidx = (lane < cnt) ? csr[base + lane] : 0;
            int t = 0;
            for (; t + 8 <= cnt; t += 8) {
                unsigned r[8];
#pragma unroll
                for (int u = 0; u < 8; u++) {
                    int s = __shfl_sync(FULL, myidx, t + u);
                    r[u] = *(const unsigned*)(A + (size_t)s * D + col);
                }
#pragma unroll
                for (int u = 0; u < 8; u++) acc_fp8x4(acc, r[u]);
            }
            for (; t < cnt; t++) {
                int s = __shfl_sync(FULL, myidx, t);
                acc_fp8x4(acc, *(const unsigned*)(A + (size_t)s * D + col));
            }
        }

        float sc = isq[w];
        float post = SCALE_OQ ? rsqrtf((float)max(outc[w], 1)) : 1.0f;
        float4 bb = *(const float4*)(b + col);
        float q0 = fmaxf(fmaf(acc.x, sc, bb.x), 0.0f) * post;
        float q1 = fmaxf(fmaf(acc.y, sc, bb.y), 0.0f) * post;
        float q2 = fmaxf(fmaf(acc.z, sc, bb.z), 0.0f) * post;
        float q3 = fmaxf(fmaf(acc.w, sc, bb.w), 0.0f) * post;

        if (!DO_POOL) {
            unsigned o = (unsigned)pack_fp8x2(q0, q1) |
                         ((unsigned)pack_fp8x2(q2, q3) << 16);
            *(unsigned*)(out + (size_t)w * D + col) = o;
        } else {
            int gidx = n2g[w] * D + col;
            atomicAdd(&sacc[gidx + 0], q0);
            atomicAdd(&sacc[gidx + 1], q1);
            atomicAdd(&sacc[gidx + 2], q2);
            atomicAdd(&sacc[gidx + 3], q3);
        }
    }

    if (DO_POOL) {
        __syncthreads();
        for (int j = threadIdx.x; j < G * D; j += 256) {
            float v = sacc[j];
            if (v != 0.0f) atomicAdd(&g_sums[j], v);
        }
    }
}

// ---------------- final: counts via binary search, mean -> linear -> softmax --
__global__ __launch_bounds__(128)
void k_final(const float* __restrict__ Wl, const float* __restrict__ bl,
             const int* __restrict__ n2g, int n, float* __restrict__ out) {
    __shared__ float hg[G * D];
    __shared__ float logits[G * C];
    __shared__ float scnt[G];
    int tid = threadIdx.x;
    if (tid < G) {
        int lo = 0, hi = n;
        while (lo < hi) { int m = (lo + hi) >> 1; if (n2g[m] < tid) lo = m + 1; else hi = m; }
        int lo2 = lo, hi2 = n;
        while (lo2 < hi2) { int m = (lo2 + hi2) >> 1; if (n2g[m] < tid + 1) lo2 = m + 1; else hi2 = m; }
        scnt[tid] = fmaxf((float)(lo2 - lo), 1.0f);
    }
    __syncthreads();
#pragma unroll
    for (int g = 0; g < G; g++)
        hg[g * D + tid] = g_sums[g * D + tid] / scnt[g];
    __syncthreads();
    if (tid < G * C) {
        int g = tid / C, c = tid % C;
        float acc = bl[c];
        for (int k = 0; k < D; k++) acc = fmaf(hg[g * D + k], Wl[k * C + c], acc);
        logits[tid] = acc;
    }
    __syncthreads();
    if (tid < G) {
        float m = -1e30f;
        for (int c = 0; c < C; c++) m = fmaxf(m, logits[tid * C + c]);
        float s = 0.0f;
        float e[C];
        for (int c = 0; c < C; c++) { e[c] = expf(logits[tid * C + c] - m); s += e[c]; }
        float inv = 1.0f / s;
        for (int c = 0; c < C; c++) out[tid * C + c] = e[c] * inv;
    }
}

// ---------------- launch --------------------------------------------------------
extern "C" void kernel_launch(void* const* d_in, const int* in_sizes, int n_in,
                              void* d_out, int out_size) {
    const float* x   = (const float*)d_in[0];
    const int*   ei  = (const int*)d_in[1];
    const int*   n2g = (const int*)d_in[2];
    const float* W1  = (const float*)d_in[3];
    const float* b1  = (const float*)d_in[4];
    const float* W2  = (const float*)d_in[5];
    const float* b2  = (const float*)d_in[6];
    const float* Wl  = (const float*)d_in[7];
    const float* bl  = (const float*)d_in[8];
    float* out = (float*)d_out;

    const int N = in_sizes[2];
    const int E = in_sizes[1] / 2;

    float* inq  = nullptr; cudaGetSymbolAddress((void**)&inq,  g_in_isqrt);
    unsigned char* hA = nullptr; cudaGetSymbolAddress((void**)&hA, g_h8A);
    unsigned char* hB = nullptr; cudaGetSymbolAddress((void**)&hB, g_h8B);
    __half* w1h = nullptr; cudaGetSymbolAddress((void**)&w1h, g_W1hi);
    __half* w1l = nullptr; cudaGetSymbolAddress((void**)&w1l, g_W1lo);
    __half* w2h = nullptr; cudaGetSymbolAddress((void**)&w2h, g_W2hi);
    __half* w2l = nullptr; cudaGetSymbolAddress((void**)&w2l, g_W2lo);
    float* sums = nullptr; cudaGetSymbolAddress((void**)&sums, g_sums);
    int* outc = nullptr; cudaGetSymbolAddress((void**)&outc, g_outcnt);
    int* inc  = nullptr; cudaGetSymbolAddress((void**)&inc,  g_incnt);
    int* rowp = nullptr; cudaGetSymbolAddress((void**)&rowp, g_rowptr);
    int* cur  = nullptr; cudaGetSymbolAddress((void**)&cur,  g_cursor);
    int* csr  = nullptr; cudaGetSymbolAddress((void**)&csr,  g_csr);
    int* bsum = nullptr; cudaGetSymbolAddress((void**)&bsum, g_bsums);

    const int nb = (N + 255) / 256;
    const int ntiles = (N + 127) / 128;
    const int gemmBlocks = 296;
    const int gatherBlocks = (N * 32 + 255) / 256;
    const int smemGemm = 3 * 128 * LDA * (int)sizeof(__half);

    static cudaStream_t s1;
    static cudaEvent_t ev_fork, ev_csr;
    static int s_init = 0;
    if (!s_init) {
        cudaFuncSetAttribute(k_gemm_tc,
                             cudaFuncAttributeMaxDynamicSharedMemorySize, smemGemm);
        cudaFuncSetAttribute(k_gemm_tc8,
                             cudaFuncAttributeMaxDynamicSharedMemorySize, smemGemm);
        cudaStreamCreateWithFlags(&s1, cudaStreamNonBlocking);
        cudaEventCreateWithFlags(&ev_fork, cudaEventDisableTiming);
        cudaEventCreateWithFlags(&ev_csr, cudaEventDisableTiming);
        s_init = 1;
    }

    // 1: setup (main)
    k_setup<<<nb, 256>>>(outc, inc, N, sums, W1, W2, w1h, w1l, w2h, w2l);
    cudaEventRecord(ev_fork, 0);
    cudaStreamWaitEvent(s1, ev_fork, 0);

    // 2: out-degree histogram (main) — only dependency of gemm1
    k_degout<<<(E + 255) / 256, 256>>>(ei, E, outc);
    // 3: in-degree histogram (s1) — feeds CSR chain
    k_degin<<<(E + 255) / 256, 256, 0, s1>>>(ei, E, inc);

    // 4 (profiled slot): layer-1 GEMM (tensor cores)
    k_gemm_tc<<<gemmBlocks, 256, smemGemm>>>(x, outc, w1h, w1l, hA, N, ntiles);

    // 5..7: CSR chain on s1
    k_scan1<<<nb, 256, 0, s1>>>(inc, N, bsum);
    k_scan3<<<nb, 256, 0, s1>>>(inc, N, nb, E, bsum, rowp, cur, inq);
    k_fill<<<(E + 255) / 256, 256, 0, s1>>>(ei, E, cur, csr);

    cudaEventRecord(ev_csr, s1);
    cudaStreamWaitEvent(0, ev_csr, 0);

    // 8..10: gather1 (folds oq), gemm2, gather2 + fused pool
    k_gather<1, 0><<<gatherBlocks, 256>>>(csr, rowp, hA, inq, b1, outc, hB, N, n2g);
    k_gemm_tc8<<<gemmBlocks, 256, smemGemm>>>(hB, w2h, w2l, hA, N, ntiles);
    k_gather<0, 1><<<gatherBlocks, 256>>>(csr, rowp, hA, inq, b2, outc, hB, N, n2g);

    // 11: head
    k_final<<<1, 128>>>(Wl, bl, n2g, N, out);
}

// round 15
// speedup vs baseline: 1.1729x; 1.0156x over previous
#include <cuda_runtime.h>
#include <cuda_fp16.h>
#include <cuda_fp8.h>

#define NN 50000
#define EE 800000
#define D  128
#define G  8
#define C  10

// ---------------- scratch (static device globals; no allocs allowed) --------
__device__ float         g_in_isqrt[NN];
__device__ unsigned char g_h8A[NN * D];
__device__ unsigned char g_h8B[NN * D];
__device__ __half        g_W1h[D * D];
__device__ __half        g_W2h[D * D];
__device__ float         g_sums[G * D];
__device__ int           g_outcnt[NN];
__device__ int           g_incnt[NN];
__device__ int           g_rowptr[NN + 1];
__device__ int           g_cursor[NN];
__device__ int           g_csr[EE];
__device__ int           g_bsums[256];

// ---------------- fp8 helpers ---------------------------------------------------
__device__ __forceinline__ unsigned short pack_fp8x2(float a, float b) {
    float2 f = make_float2(a, b);
    return __nv_cvt_float2_to_fp8x2(f, __NV_SATFINITE, __NV_E4M3);
}
__device__ __forceinline__ float2 unpack_fp8x2(unsigned v) {
    __half2_raw hr = __nv_cvt_fp8x2_to_halfraw2((__nv_fp8x2_storage_t)v, __NV_E4M3);
    return __half22float2(*(__half2*)&hr);
}
__device__ __forceinline__ __half2 fp8x2_to_h2(unsigned v) {
    __half2_raw hr = __nv_cvt_fp8x2_to_halfraw2((__nv_fp8x2_storage_t)v, __NV_E4M3);
    return *(__half2*)&hr;
}

// ---------------- setup: zero degree arrays + pool sums, convert weights ------
__global__ __launch_bounds__(256)
void k_setup(int* __restrict__ outc, int* __restrict__ inc, int n,
             float* __restrict__ sums,
             const float* __restrict__ W1, const float* __restrict__ W2,
             __half* __restrict__ w1h, __half* __restrict__ w2h) {
    int i = blockIdx.x * 256 + threadIdx.x;
    if (i < n) { outc[i] = 0; inc[i] = 0; }
    if (i < G * D) sums[i] = 0.0f;
    if (i < D * D) {
        int k = i >> 7, nn = i & 127;
        w1h[nn * D + k] = __float2half_rn(W1[i]);
        w2h[nn * D + k] = __float2half_rn(W2[i]);
    }
}

// ---------------- degree histograms (split: out on main, in on s1) ------------
__global__ void k_degout(const int* __restrict__ ei, int E, int* __restrict__ outc) {
    int e = blockIdx.x * blockDim.x + threadIdx.x;
    if (e < E) atomicAdd(&outc[ei[e]], 1);
}
__global__ void k_degin(const int* __restrict__ ei, int E, int* __restrict__ inc) {
    int e = blockIdx.x * blockDim.x + threadIdx.x;
    if (e < E) atomicAdd(&inc[ei[E + e]], 1);
}

// ---------------- scan helpers -------------------------------------------------
__device__ __forceinline__ int warp_incl_scan(int v, int lane) {
#pragma unroll
    for (int o = 1; o < 32; o <<= 1) {
        int t = __shfl_up_sync(0xffffffffu, v, o);
        if (lane >= o) v += t;
    }
    return v;
}

__device__ __forceinline__ int block_incl_scan(int v, int tid, int* ws) {
    int lane = tid & 31, wid = tid >> 5;
    int s = warp_incl_scan(v, lane);
    if (lane == 31) ws[wid] = s;
    __syncthreads();
    if (wid == 0) {
        int t = (lane < 8) ? ws[lane] : 0;
        t = warp_incl_scan(t, lane);
        if (lane < 8) ws[lane] = t;
    }
    __syncthreads();
    return s + (wid > 0 ? ws[wid - 1] : 0);
}

__global__ __launch_bounds__(256)
void k_scan1(const int* __restrict__ inc, int n, int* __restrict__ bsums) {
    __shared__ int ws[8];
    int tid = threadIdx.x;
    int i = blockIdx.x * 256 + tid;
    int v = (i < n) ? inc[i] : 0;
    int incl = block_incl_scan(v, tid, ws);
    if (tid == 255) bsums[blockIdx.x] = incl;
}

__global__ __launch_bounds__(256)
void k_scan3(const int* __restrict__ inc, int n, int nb, int E,
             const int* __restrict__ bsums, int* __restrict__ rowp,
             int* __restrict__ cur, float* __restrict__ iq) {
    __shared__ int ws[8];
    __shared__ int soff[256];
    int tid = threadIdx.x;

    int vb = (tid < nb) ? bsums[tid] : 0;
    int inclb = block_incl_scan(vb, tid, ws);
    soff[tid] = inclb - vb;
    __syncthreads();
    int blockoff = soff[blockIdx.x];
    __syncthreads();

    int i = blockIdx.x * 256 + tid;
    int v = (i < n) ? inc[i] : 0;
    int incl = block_incl_scan(v, tid, ws);
    if (i < n) {
        int ex = incl - v + blockoff;
        rowp[i] = ex;
        cur[i] = ex;
        iq[i] = rsqrtf((float)max(v, 1));
    }
    if (blockIdx.x == 0 && tid == 0) rowp[n] = E;
}

// ---------------- CSR fill -----------------------------------------------------
__global__ void k_fill(const int* __restrict__ ei, int E,
                       int* __restrict__ cur, int* __restrict__ csr) {
    int e = blockIdx.x * blockDim.x + threadIdx.x;
    if (e < E) {
        int d = ei[E + e];
        int pos = atomicAdd(&cur[d], 1);
        csr[pos] = ei[e];
    }
}

// ---------------- MMA helper ----------------------------------------------------
__device__ __forceinline__ void mma16816(float* c, const unsigned* a,
                                         unsigned b0, unsigned b1) {
    asm volatile(
        "mma.sync.aligned.m16n8k16.row.col.f32.f16.f16.f32 "
        "{%0,%1,%2,%3}, {%4,%5,%6,%7}, {%8,%9}, {%0,%1,%2,%3};"
        : "+f"(c[0]), "+f"(c[1]), "+f"(c[2]), "+f"(c[3])
        : "r"(a[0]), "r"(a[1]), "r"(a[2]), "r"(a[3]), "r"(b0), "r"(b1));
}

#define LDA 136   // padded smem stride in halves

// ---------------- common MMA phase (single fp16 weight, fp8 output) -----------
__device__ __forceinline__ void mma_phase(
    const __half* As, const __half* Bh,
    unsigned char* __restrict__ Cm, int rowBase, int nrows,
    int wr, int wc, int g, int tg) {
    float acc[2][8][4];
#pragma unroll
    for (int mt = 0; mt < 2; mt++)
#pragma unroll
        for (int nt = 0; nt < 8; nt++)
#pragma unroll
            for (int q = 0; q < 4; q++) acc[mt][nt][q] = 0.0f;

#pragma unroll
    for (int ks = 0; ks < 8; ks++) {
        const int k0 = ks * 16;
        unsigned a[2][4];
#pragma unroll
        for (int mt = 0; mt < 2; mt++) {
            const __half* pr = As + (wr * 32 + mt * 16 + g) * LDA + k0 + tg * 2;
            a[mt][0] = *(const unsigned*)(pr);
            a[mt][1] = *(const unsigned*)(pr + 8 * LDA);
            a[mt][2] = *(const unsigned*)(pr + 8);
            a[mt][3] = *(const unsigned*)(pr + 8 * LDA + 8);
        }
#pragma unroll
        for (int nt = 0; nt < 8; nt++) {
            const int n = wc * 64 + nt * 8 + g;
            const __half* ph = Bh + n * LDA + k0 + tg * 2;
            unsigned bh0 = *(const unsigned*)(ph);
            unsigned bh1 = *(const unsigned*)(ph + 8);
#pragma unroll
            for (int mt = 0; mt < 2; mt++)
                mma16816(acc[mt][nt], a[mt], bh0, bh1);
        }
    }

#pragma unroll
    for (int mt = 0; mt < 2; mt++) {
        int r0 = rowBase + wr * 32 + mt * 16 + g;
        int r1 = r0 + 8;
#pragma unroll
        for (int nt = 0; nt < 8; nt++) {
            int col = wc * 64 + nt * 8 + tg * 2;
            if (r0 < nrows)
                *(unsigned short*)(Cm + (size_t)r0 * D + col) =
                    pack_fp8x2(acc[mt][nt][0], acc[mt][nt][1]);
            if (r1 < nrows)
                *(unsigned short*)(Cm + (size_t)r1 * D + col) =
                    pack_fp8x2(acc[mt][nt][2], acc[mt][nt][3]);
        }
    }
}

// ---------------- layer-1 GEMM: fp32 A scaled by rsqrt(outdeg), fp8 out --------
// one 128-row tile per block
__global__ __launch_bounds__(256)
void k_gemm_tc(const float* __restrict__ A, const int* __restrict__ outc,
               const __half* __restrict__ Whi,
               unsigned char* __restrict__ Cm, int nrows) {
    extern __shared__ __half sm[];
    __half* As = sm;
    __half* Bh = sm + 128 * LDA;

    const int tid = threadIdx.x;
    const int wid = tid >> 5, lane = tid & 31;
    const int wr = wid >> 1, wc = wid & 1;
    const int g = lane >> 2, tg = lane & 3;

    for (int j = tid; j < 2048; j += 256) {
        int n = j >> 4, kc = (j & 15) * 8;
        *(uint4*)(Bh + n * LDA + kc) = *(const uint4*)(Whi + n * D + kc);
    }

    const int rowBase = blockIdx.x * 128;
    for (int j = tid; j < 4096; j += 256) {
        int r = j >> 5, kc = (j & 31) * 4;
        int gr = rowBase + r;
        __half2 o[2];
        if (gr < nrows) {
            float s = rsqrtf((float)max(outc[gr], 1));
            float4 v = *(const float4*)(A + (size_t)gr * D + kc);
            o[0] = __floats2half2_rn(v.x * s, v.y * s);
            o[1] = __floats2half2_rn(v.z * s, v.w * s);
        } else {
            o[0] = __half2half2(__float2half(0.f));
            o[1] = o[0];
        }
        *(uint2*)(As + r * LDA + kc) = *(uint2*)o;
    }
    __syncthreads();
    mma_phase(As, Bh, Cm, rowBase, nrows, wr, wc, g, tg);
}

// ---------------- layer-2 GEMM: fp8 A converted in smem load, fp8 out ----------
__global__ __launch_bounds__(256)
void k_gemm_tc8(const unsigned char* __restrict__ A,
                const __half* __restrict__ Whi,
                unsigned char* __restrict__ Cm, int nrows) {
    extern __shared__ __half sm[];
    __half* As = sm;
    __half* Bh = sm + 128 * LDA;

    const int tid = threadIdx.x;
    const int wid = tid >> 5, lane = tid & 31;
    const int wr = wid >> 1, wc = wid & 1;
    const int g = lane >> 2, tg = lane & 3;

    for (int j = tid; j < 2048; j += 256) {
        int n = j >> 4, kc = (j & 15) * 8;
        *(uint4*)(Bh + n * LDA + kc) = *(const uint4*)(Whi + n * D + kc);
    }

    const int rowBase = blockIdx.x * 128;
    for (int j = tid; j < 2048; j += 256) {
        int r = j >> 4, kc = (j & 15) * 8;
        int gr = rowBase + r;
        __half2 h[4];
        if (gr < nrows) {
            uint2 raw = *(const uint2*)(A + (size_t)gr * D + kc);
            h[0] = fp8x2_to_h2(raw.x & 0xffffu);
            h[1] = fp8x2_to_h2(raw.x >> 16);
            h[2] = fp8x2_to_h2(raw.y & 0xffffu);
            h[3] = fp8x2_to_h2(raw.y >> 16);
        } else {
            h[0] = __half2half2(__float2half(0.f));
            h[1] = h[0]; h[2] = h[0]; h[3] = h[0];
        }
        *(uint4*)(As + r * LDA + kc) = *(uint4*)h;
    }
    __syncthreads();
    mma_phase(As, Bh, Cm, rowBase, nrows, wr, wc, g, tg);
}

// ---------------- gather accumulate helper --------------------------------------
__device__ __forceinline__ void acc_fp8x4(float4& acc, unsigned r) {
    float2 lo = unpack_fp8x2(r & 0xffffu);
    float2 hi = unpack_fp8x2(r >> 16);
    acc.x += lo.x; acc.y += lo.y; acc.z += hi.x; acc.w += hi.y;
}

// ---------------- gather + fused epilogue (+ optional fused pooling) ----------
template <int SCALE_OQ, int DO_POOL>
__global__ __launch_bounds__(256)
void k_gather(const int* __restrict__ csr, const int* __restrict__ rowp,
              const unsigned char* __restrict__ A, const float* __restrict__ isq,
              const float* __restrict__ b, const int* __restrict__ outc,
              unsigned char* __restrict__ out, int n, const int* __restrict__ n2g) {
    __shared__ float sacc[DO_POOL ? G * D : 1];
    if (DO_POOL) {
        for (int j = threadIdx.x; j < G * D; j += 256) sacc[j] = 0.0f;
        __syncthreads();
    }

    int w = (blockIdx.x * blockDim.x + threadIdx.x) >> 5;
    int lane = threadIdx.x & 31;
    int col = lane * 4;
    const unsigned FULL = 0xffffffffu;

    if (w < n) {
        int s0 = rowp[w], s1 = rowp[w + 1];
        float4 acc = make_float4(0.f, 0.f, 0.f, 0.f);

        for (int base = s0; base < s1; base += 32) {
            int cnt = min(32, s1 - base);
            int myidx = (lane < cnt) ? csr[base + lane] : 0;
            int t = 0;
            for (; t + 8 <= cnt; t += 8) {
                unsigned r[8];
#pragma unroll
                for (int u = 0; u < 8; u++) {
                    int s = __shfl_sync(FULL, myidx, t + u);
                    r[u] = *(const unsigned*)(A + (size_t)s * D + col);
                }
#pragma unroll
                for (int u = 0; u < 8; u++) acc_fp8x4(acc, r[u]);
            }
            for (; t < cnt; t++) {
                int s = __shfl_sync(FULL, myidx, t);
                acc_fp8x4(acc, *(const unsigned*)(A + (size_t)s * D + col));
            }
        }

        float sc = isq[w];
        float post = SCALE_OQ ? rsqrtf((float)max(outc[w], 1)) : 1.0f;
        float4 bb = *(const float4*)(b + col);
        float q0 = fmaxf(fmaf(acc.x, sc, bb.x), 0.0f) * post;
        float q1 = fmaxf(fmaf(acc.y, sc, bb.y), 0.0f) * post;
        float q2 = fmaxf(fmaf(acc.z, sc, bb.z), 0.0f) * post;
        float q3 = fmaxf(fmaf(acc.w, sc, bb.w), 0.0f) * post;

        if (!DO_POOL) {
            unsigned o = (unsigned)pack_fp8x2(q0, q1) |
                         ((unsigned)pack_fp8x2(q2, q3) << 16);
            *(unsigned*)(out + (size_t)w * D + col) = o;
        } else {
            int gidx = n2g[w] * D + col;
            atomicAdd(&sacc[gidx + 0], q0);
            atomicAdd(&sacc[gidx + 1], q1);
            atomicAdd(&sacc[gidx + 2], q2);
            atomicAdd(&sacc[gidx + 3], q3);
        }
    }

    if (DO_POOL) {
        __syncthreads();
        for (int j = threadIdx.x; j < G * D; j += 256) {
            float v = sacc[j];
            if (v != 0.0f) atomicAdd(&g_sums[j], v);
        }
    }
}

// ---------------- final: counts via binary search, mean -> linear -> softmax --
__global__ __launch_bounds__(128)
void k_final(const float* __restrict__ Wl, const float* __restrict__ bl,
             const int* __restrict__ n2g, int n, float* __restrict__ out) {
    __shared__ float hg[G * D];
    __shared__ float logits[G * C];
    __shared__ float scnt[G];
    int tid = threadIdx.x;
    if (tid < G) {
        int lo = 0, hi = n;
        while (lo < hi) { int m = (lo + hi) >> 1; if (n2g[m] < tid) lo = m + 1; else hi = m; }
        int lo2 = lo, hi2 = n;
        while (lo2 < hi2) { int m = (lo2 + hi2) >> 1; if (n2g[m] < tid + 1) lo2 = m + 1; else hi2 = m; }
        scnt[tid] = fmaxf((float)(lo2 - lo), 1.0f);
    }
    __syncthreads();
#pragma unroll
    for (int g = 0; g < G; g++)
        hg[g * D + tid] = g_sums[g * D + tid] / scnt[g];
    __syncthreads();
    if (tid < G * C) {
        int g = tid / C, c = tid % C;
        float acc = bl[c];
        for (int k = 0; k < D; k++) acc = fmaf(hg[g * D + k], Wl[k * C + c], acc);
        logits[tid] = acc;
    }
    __syncthreads();
    if (tid < G) {
        float m = -1e30f;
        for (int c = 0; c < C; c++) m = fmaxf(m, logits[tid * C + c]);
        float s = 0.0f;
        float e[C];
        for (int c = 0; c < C; c++) { e[c] = expf(logits[tid * C + c] - m); s += e[c]; }
        float inv = 1.0f / s;
        for (int c = 0; c < C; c++) out[tid * C + c] = e[c] * inv;
    }
}

// ---------------- launch --------------------------------------------------------
extern "C" void kernel_launch(void* const* d_in, const int* in_sizes, int n_in,
                              void* d_out, int out_size) {
    const float* x   = (const float*)d_in[0];
    const int*   ei  = (const int*)d_in[1];
    const int*   n2g = (const int*)d_in[2];
    const float* W1  = (const float*)d_in[3];
    const float* b1  = (const float*)d_in[4];
    const float* W2  = (const float*)d_in[5];
    const float* b2  = (const float*)d_in[6];
    const float* Wl  = (const float*)d_in[7];
    const float* bl  = (const float*)d_in[8];
    float* out = (float*)d_out;

    const int N = in_sizes[2];
    const int E = in_sizes[1] / 2;

    float* inq  = nullptr; cudaGetSymbolAddress((void**)&inq,  g_in_isqrt);
    unsigned char* hA = nullptr; cudaGetSymbolAddress((void**)&hA, g_h8A);
    unsigned char* hB = nullptr; cudaGetSymbolAddress((void**)&hB, g_h8B);
    __half* w1h = nullptr; cudaGetSymbolAddress((void**)&w1h, g_W1h);
    __half* w2h = nullptr; cudaGetSymbolAddress((void**)&w2h, g_W2h);
    float* sums = nullptr; cudaGetSymbolAddress((void**)&sums, g_sums);
    int* outc = nullptr; cudaGetSymbolAddress((void**)&outc, g_outcnt);
    int* inc  = nullptr; cudaGetSymbolAddress((void**)&inc,  g_incnt);
    int* rowp = nullptr; cudaGetSymbolAddress((void**)&rowp, g_rowptr);
    int* cur  = nullptr; cudaGetSymbolAddress((void**)&cur,  g_cursor);
    int* csr  = nullptr; cudaGetSymbolAddress((void**)&csr,  g_csr);
    int* bsum = nullptr; cudaGetSymbolAddress((void**)&bsum, g_bsums);

    const int nb = (N + 255) / 256;
    const int ntiles = (N + 127) / 128;
    const int gatherBlocks = (N * 32 + 255) / 256;
    const int smemGemm = 2 * 128 * LDA * (int)sizeof(__half);   // 69632

    static cudaStream_t s1;
    static cudaEvent_t ev_fork, ev_csr;
    static int s_init = 0;
    if (!s_init) {
        cudaFuncSetAttribute(k_gemm_tc,
                             cudaFuncAttributeMaxDynamicSharedMemorySize, smemGemm);
        cudaFuncSetAttribute(k_gemm_tc8,
                             cudaFuncAttributeMaxDynamicSharedMemorySize, smemGemm);
        cudaStreamCreateWithFlags(&s1, cudaStreamNonBlocking);
        cudaEventCreateWithFlags(&ev_fork, cudaEventDisableTiming);
        cudaEventCreateWithFlags(&ev_csr, cudaEventDisableTiming);
        s_init = 1;
    }

    // 1: setup (main)
    k_setup<<<nb, 256>>>(outc, inc, N, sums, W1, W2, w1h, w2h);
    cudaEventRecord(ev_fork, 0);
    cudaStreamWaitEvent(s1, ev_fork, 0);

    // 2: out-degree histogram (main) — only dependency of gemm1
    k_degout<<<(E + 255) / 256, 256>>>(ei, E, outc);
    // 3: in-degree histogram (s1) — feeds CSR chain
    k_degin<<<(E + 255) / 256, 256, 0, s1>>>(ei, E, inc);

    // 4 (profiled slot): layer-1 GEMM (tensor cores, single fp16 weight)
    k_gemm_tc<<<ntiles, 256, smemGemm>>>(x, outc, w1h, hA, N);

    // 5..7: CSR chain on s1
    k_scan1<<<nb, 256, 0, s1>>>(inc, N, bsum);
    k_scan3<<<nb, 256, 0, s1>>>(inc, N, nb, E, bsum, rowp, cur, inq);
    k_fill<<<(E + 255) / 256, 256, 0, s1>>>(ei, E, cur, csr);

    cudaEventRecord(ev_csr, s1);
    cudaStreamWaitEvent(0, ev_csr, 0);

    // 8..10: gather1 (folds oq), gemm2, gather2 + fused pool
    k_gather<1, 0><<<gatherBlocks, 256>>>(csr, rowp, hA, inq, b1, outc, hB, N, n2g);
    k_gemm_tc8<<<ntiles, 256, smemGemm>>>(hB, w2h, hA, N);
    k_gather<0, 1><<<gatherBlocks, 256>>>(csr, rowp, hA, inq, b2, outc, hB, N, n2g);

    // 11: head
    k_final<<<1, 128>>>(Wl, bl, n2g, N, out);
}

// round 16
// speedup vs baseline: 1.2372x; 1.0548x over previous
#include <cuda_runtime.h>
#include <cuda_fp16.h>
#include <cuda_fp8.h>

#define NN 50000
#define EE 800000
#define D  128
#define G  8
#define C  10

// ---------------- scratch (static device globals; no allocs allowed) --------
__device__ float         g_in_isqrt[NN];
__device__ unsigned char g_h8A[NN * D];
__device__ unsigned char g_h8B[NN * D];
__device__ __half        g_W1h[D * D];
__device__ __half        g_W2h[D * D];
__device__ float         g_sums[G * D];
__device__ int           g_outcnt[NN];
__device__ int           g_incnt[NN];
__device__ int           g_rowptr[NN + 1];
__device__ int           g_cursor[NN];
__device__ int           g_csr[EE];
__device__ int           g_bsums[256];

// ---------------- fp8 helpers ---------------------------------------------------
__device__ __forceinline__ unsigned short pack_fp8x2(float a, float b) {
    float2 f = make_float2(a, b);
    return __nv_cvt_float2_to_fp8x2(f, __NV_SATFINITE, __NV_E4M3);
}
__device__ __forceinline__ float2 unpack_fp8x2(unsigned v) {
    __half2_raw hr = __nv_cvt_fp8x2_to_halfraw2((__nv_fp8x2_storage_t)v, __NV_E4M3);
    return __half22float2(*(__half2*)&hr);
}
__device__ __forceinline__ __half2 fp8x2_to_h2(unsigned v) {
    __half2_raw hr = __nv_cvt_fp8x2_to_halfraw2((__nv_fp8x2_storage_t)v, __NV_E4M3);
    return *(__half2*)&hr;
}

// ---------------- setup: zero degree arrays + pool sums, convert weights ------
__global__ __launch_bounds__(256)
void k_setup(int* __restrict__ outc, int* __restrict__ inc, int n,
             float* __restrict__ sums,
             const float* __restrict__ W1, const float* __restrict__ W2,
             __half* __restrict__ w1h, __half* __restrict__ w2h) {
    int i = blockIdx.x * 256 + threadIdx.x;
    if (i < n) { outc[i] = 0; inc[i] = 0; }
    if (i < G * D) sums[i] = 0.0f;
    if (i < D * D) {
        int k = i >> 7, nn = i & 127;
        w1h[nn * D + k] = __float2half_rn(W1[i]);
        w2h[nn * D + k] = __float2half_rn(W2[i]);
    }
}

// ---------------- degree histograms (split: out on main, in on s1) ------------
__global__ void k_degout(const int* __restrict__ ei, int E, int* __restrict__ outc) {
    int e = blockIdx.x * blockDim.x + threadIdx.x;
    if (e < E) atomicAdd(&outc[ei[e]], 1);
}
__global__ void k_degin(const int* __restrict__ ei, int E, int* __restrict__ inc) {
    int e = blockIdx.x * blockDim.x + threadIdx.x;
    if (e < E) atomicAdd(&inc[ei[E + e]], 1);
}

// ---------------- scan helpers -------------------------------------------------
__device__ __forceinline__ int warp_incl_scan(int v, int lane) {
#pragma unroll
    for (int o = 1; o < 32; o <<= 1) {
        int t = __shfl_up_sync(0xffffffffu, v, o);
        if (lane >= o) v += t;
    }
    return v;
}

__device__ __forceinline__ int block_incl_scan(int v, int tid, int* ws) {
    int lane = tid & 31, wid = tid >> 5;
    int s = warp_incl_scan(v, lane);
    if (lane == 31) ws[wid] = s;
    __syncthreads();
    if (wid == 0) {
        int t = (lane < 8) ? ws[lane] : 0;
        t = warp_incl_scan(t, lane);
        if (lane < 8) ws[lane] = t;
    }
    __syncthreads();
    return s + (wid > 0 ? ws[wid - 1] : 0);
}

__global__ __launch_bounds__(256)
void k_scan1(const int* __restrict__ inc, int n, int* __restrict__ bsums) {
    __shared__ int ws[8];
    int tid = threadIdx.x;
    int i = blockIdx.x * 256 + tid;
    int v = (i < n) ? inc[i] : 0;
    int incl = block_incl_scan(v, tid, ws);
    if (tid == 255) bsums[blockIdx.x] = incl;
}

__global__ __launch_bounds__(256)
void k_scan3(const int* __restrict__ inc, int n, int nb, int E,
             const int* __restrict__ bsums, int* __restrict__ rowp,
             int* __restrict__ cur, float* __restrict__ iq) {
    __shared__ int ws[8];
    __shared__ int soff[256];
    int tid = threadIdx.x;

    int vb = (tid < nb) ? bsums[tid] : 0;
    int inclb = block_incl_scan(vb, tid, ws);
    soff[tid] = inclb - vb;
    __syncthreads();
    int blockoff = soff[blockIdx.x];
    __syncthreads();

    int i = blockIdx.x * 256 + tid;
    int v = (i < n) ? inc[i] : 0;
    int incl = block_incl_scan(v, tid, ws);
    if (i < n) {
        int ex = incl - v + blockoff;
        rowp[i] = ex;
        cur[i] = ex;
        iq[i] = rsqrtf((float)max(v, 1));
    }
    if (blockIdx.x == 0 && tid == 0) rowp[n] = E;
}

// ---------------- CSR fill -----------------------------------------------------
__global__ void k_fill(const int* __restrict__ ei, int E,
                       int* __restrict__ cur, int* __restrict__ csr) {
    int e = blockIdx.x * blockDim.x + threadIdx.x;
    if (e < E) {
        int d = ei[E + e];
        int pos = atomicAdd(&cur[d], 1);
        csr[pos] = ei[e];
    }
}

// ---------------- MMA helper ----------------------------------------------------
__device__ __forceinline__ void mma16816(float* c, const unsigned* a,
                                         unsigned b0, unsigned b1) {
    asm volatile(
        "mma.sync.aligned.m16n8k16.row.col.f32.f16.f16.f32 "
        "{%0,%1,%2,%3}, {%4,%5,%6,%7}, {%8,%9}, {%0,%1,%2,%3};"
        : "+f"(c[0]), "+f"(c[1]), "+f"(c[2]), "+f"(c[3])
        : "r"(a[0]), "r"(a[1]), "r"(a[2]), "r"(a[3]), "r"(b0), "r"(b1));
}

#define LDA 136   // padded smem stride in halves

// ---------------- common MMA phase (single fp16 weight, fp8 output) -----------
__device__ __forceinline__ void mma_phase(
    const __half* As, const __half* Bh,
    unsigned char* __restrict__ Cm, int rowBase, int nrows,
    int wr, int wc, int g, int tg) {
    float acc[2][8][4];
#pragma unroll
    for (int mt = 0; mt < 2; mt++)
#pragma unroll
        for (int nt = 0; nt < 8; nt++)
#pragma unroll
            for (int q = 0; q < 4; q++) acc[mt][nt][q] = 0.0f;

#pragma unroll
    for (int ks = 0; ks < 8; ks++) {
        const int k0 = ks * 16;
        unsigned a[2][4];
#pragma unroll
        for (int mt = 0; mt < 2; mt++) {
            const __half* pr = As + (wr * 32 + mt * 16 + g) * LDA + k0 + tg * 2;
            a[mt][0] = *(const unsigned*)(pr);
            a[mt][1] = *(const unsigned*)(pr + 8 * LDA);
            a[mt][2] = *(const unsigned*)(pr + 8);
            a[mt][3] = *(const unsigned*)(pr + 8 * LDA + 8);
        }
#pragma unroll
        for (int nt = 0; nt < 8; nt++) {
            const int n = wc * 64 + nt * 8 + g;
            const __half* ph = Bh + n * LDA + k0 + tg * 2;
            unsigned bh0 = *(const unsigned*)(ph);
            unsigned bh1 = *(const unsigned*)(ph + 8);
#pragma unroll
            for (int mt = 0; mt < 2; mt++)
                mma16816(acc[mt][nt], a[mt], bh0, bh1);
        }
    }

#pragma unroll
    for (int mt = 0; mt < 2; mt++) {
        int r0 = rowBase + wr * 32 + mt * 16 + g;
        int r1 = r0 + 8;
#pragma unroll
        for (int nt = 0; nt < 8; nt++) {
            int col = wc * 64 + nt * 8 + tg * 2;
            if (r0 < nrows)
                *(unsigned short*)(Cm + (size_t)r0 * D + col) =
                    pack_fp8x2(acc[mt][nt][0], acc[mt][nt][1]);
            if (r1 < nrows)
                *(unsigned short*)(Cm + (size_t)r1 * D + col) =
                    pack_fp8x2(acc[mt][nt][2], acc[mt][nt][3]);
        }
    }
}

// ---------------- layer-1 GEMM: fp32 A scaled by rsqrt(outdeg), fp8 out --------
// one 128-row tile per block, 3 CTAs/SM, batched loads for MLP
__global__ __launch_bounds__(256, 3)
void k_gemm_tc(const float* __restrict__ A, const int* __restrict__ outc,
               const __half* __restrict__ Whi,
               unsigned char* __restrict__ Cm, int nrows) {
    extern __shared__ __half sm[];
    __half* As = sm;
    __half* Bh = sm + 128 * LDA;

    const int tid = threadIdx.x;
    const int wid = tid >> 5, lane = tid & 31;
    const int wr = wid >> 1, wc = wid & 1;
    const int g = lane >> 2, tg = lane & 3;

    for (int j = tid; j < 2048; j += 256) {
        int n = j >> 4, kc = (j & 15) * 8;
        *(uint4*)(Bh + n * LDA + kc) = *(const uint4*)(Whi + n * D + kc);
    }

    const int rowBase = blockIdx.x * 128;
    // 16 float4 per thread, processed in 4 batches of 4 (MLP = 8: 4 data + 4 deg)
#pragma unroll
    for (int batch = 0; batch < 4; batch++) {
        float4 vv[4];
        float ss[4];
        int rr[4], kk[4];
#pragma unroll
        for (int u = 0; u < 4; u++) {
            int j = tid + (batch * 4 + u) * 256;
            rr[u] = j >> 5;
            kk[u] = (j & 31) * 4;
            int gr = rowBase + rr[u];
            if (gr < nrows) {
                vv[u] = *(const float4*)(A + (size_t)gr * D + kk[u]);
                ss[u] = rsqrtf((float)max(outc[gr], 1));
            } else {
                vv[u] = make_float4(0.f, 0.f, 0.f, 0.f);
                ss[u] = 0.0f;
            }
        }
#pragma unroll
        for (int u = 0; u < 4; u++) {
            __half2 o[2];
            o[0] = __floats2half2_rn(vv[u].x * ss[u], vv[u].y * ss[u]);
            o[1] = __floats2half2_rn(vv[u].z * ss[u], vv[u].w * ss[u]);
            *(uint2*)(As + rr[u] * LDA + kk[u]) = *(uint2*)o;
        }
    }
    __syncthreads();
    mma_phase(As, Bh, Cm, rowBase, nrows, wr, wc, g, tg);
}

// ---------------- layer-2 GEMM: fp8 A converted in smem load, fp8 out ----------
__global__ __launch_bounds__(256, 3)
void k_gemm_tc8(const unsigned char* __restrict__ A,
                const __half* __restrict__ Whi,
                unsigned char* __restrict__ Cm, int nrows) {
    extern __shared__ __half sm[];
    __half* As = sm;
    __half* Bh = sm + 128 * LDA;

    const int tid = threadIdx.x;
    const int wid = tid >> 5, lane = tid & 31;
    const int wr = wid >> 1, wc = wid & 1;
    const int g = lane >> 2, tg = lane & 3;

    for (int j = tid; j < 2048; j += 256) {
        int n = j >> 4, kc = (j & 15) * 8;
        *(uint4*)(Bh + n * LDA + kc) = *(const uint4*)(Whi + n * D + kc);
    }

    const int rowBase = blockIdx.x * 128;
    // 8 uint2 per thread in 2 batches of 4
#pragma unroll
    for (int batch = 0; batch < 2; batch++) {
        uint2 raw[4];
        int rr[4], kk[4];
#pragma unroll
        for (int u = 0; u < 4; u++) {
            int j = tid + (batch * 4 + u) * 256;
            rr[u] = j >> 4;
            kk[u] = (j & 15) * 8;
            int gr = rowBase + rr[u];
            raw[u] = (gr < nrows)
                     ? *(const uint2*)(A + (size_t)gr * D + kk[u])
                     : make_uint2(0u, 0u);
        }
#pragma unroll
        for (int u = 0; u < 4; u++) {
            __half2 h[4];
            h[0] = fp8x2_to_h2(raw[u].x & 0xffffu);
            h[1] = fp8x2_to_h2(raw[u].x >> 16);
            h[2] = fp8x2_to_h2(raw[u].y & 0xffffu);
            h[3] = fp8x2_to_h2(raw[u].y >> 16);
            *(uint4*)(As + rr[u] * LDA + kk[u]) = *(uint4*)h;
        }
    }
    __syncthreads();
    mma_phase(As, Bh, Cm, rowBase, nrows, wr, wc, g, tg);
}

// ---------------- gather accumulate helper --------------------------------------
__device__ __forceinline__ void acc_fp8x4(float4& acc, unsigned r) {
    float2 lo = unpack_fp8x2(r & 0xffffu);
    float2 hi = unpack_fp8x2(r >> 16);
    acc.x += lo.x; acc.y += lo.y; acc.z += hi.x; acc.w += hi.y;
}

// ---------------- gather + fused epilogue (+ optional fused pooling) ----------
template <int SCALE_OQ, int DO_POOL>
__global__ __launch_bounds__(256)
void k_gather(const int* __restrict__ csr, const int* __restrict__ rowp,
              const unsigned char* __restrict__ A, const float* __restrict__ isq,
              const float* __restrict__ b, const int* __restrict__ outc,
              unsigned char* __restrict__ out, int n, const int* __restrict__ n2g) {
    __shared__ float sacc[DO_POOL ? G * D : 1];
    if (DO_POOL) {
        for (int j = threadIdx.x; j < G * D; j += 256) sacc[j] = 0.0f;
        __syncthreads();
    }

    int w = (blockIdx.x * blockDim.x + threadIdx.x) >> 5;
    int lane = threadIdx.x & 31;
    int col = lane * 4;
    const unsigned FULL = 0xffffffffu;

    if (w < n) {
        int s0 = rowp[w], s1 = rowp[w + 1];
        float4 acc = make_float4(0.f, 0.f, 0.f, 0.f);

        for (int base = s0; base < s1; base += 32) {
            int cnt = min(32, s1 - base);
            int myidx = (lane < cnt) ? csr[base + lane] : 0;
            int t = 0;
            for (; t + 8 <= cnt; t += 8) {
                unsigned r[8];
#pragma unroll
                for (int u = 0; u < 8; u++) {
                    int s = __shfl_sync(FULL, myidx, t + u);
                    r[u] = *(const unsigned*)(A + (size_t)s * D + col);
                }
#pragma unroll
                for (int u = 0; u < 8; u++) acc_fp8x4(acc, r[u]);
            }
            for (; t < cnt; t++) {
                int s = __shfl_sync(FULL, myidx, t);
                acc_fp8x4(acc, *(const unsigned*)(A + (size_t)s * D + col));
            }
        }

        float sc = isq[w];
        float post = SCALE_OQ ? rsqrtf((float)max(outc[w], 1)) : 1.0f;
        float4 bb = *(const float4*)(b + col);
        float q0 = fmaxf(fmaf(acc.x, sc, bb.x), 0.0f) * post;
        float q1 = fmaxf(fmaf(acc.y, sc, bb.y), 0.0f) * post;
        float q2 = fmaxf(fmaf(acc.z, sc, bb.z), 0.0f) * post;
        float q3 = fmaxf(fmaf(acc.w, sc, bb.w), 0.0f) * post;

        if (!DO_POOL) {
            unsigned o = (unsigned)pack_fp8x2(q0, q1) |
                         ((unsigned)pack_fp8x2(q2, q3) << 16);
            *(unsigned*)(out + (size_t)w * D + col) = o;
        } else {
            int gidx = n2g[w] * D + col;
            atomicAdd(&sacc[gidx + 0], q0);
            atomicAdd(&sacc[gidx + 1], q1);
            atomicAdd(&sacc[gidx + 2], q2);
            atomicAdd(&sacc[gidx + 3], q3);
        }
    }

    if (DO_POOL) {
        __syncthreads();
        for (int j = threadIdx.x; j < G * D; j += 256) {
            float v = sacc[j];
            if (v != 0.0f) atomicAdd(&g_sums[j], v);
        }
    }
}

// ---------------- final: counts via binary search, mean -> linear -> softmax --
__global__ __launch_bounds__(128)
void k_final(const float* __restrict__ Wl, const float* __restrict__ bl,
             const int* __restrict__ n2g, int n, float* __restrict__ out) {
    __shared__ float hg[G * D];
    __shared__ float logits[G * C];
    __shared__ float scnt[G];
    int tid = threadIdx.x;
    if (tid < G) {
        int lo = 0, hi = n;
        while (lo < hi) { int m = (lo + hi) >> 1; if (n2g[m] < tid) lo = m + 1; else hi = m; }
        int lo2 = lo, hi2 = n;
        while (lo2 < hi2) { int m = (lo2 + hi2) >> 1; if (n2g[m] < tid + 1) lo2 = m + 1; else hi2 = m; }
        scnt[tid] = fmaxf((float)(lo2 - lo), 1.0f);
    }
    __syncthreads();
#pragma unroll
    for (int g = 0; g < G; g++)
        hg[g * D + tid] = g_sums[g * D + tid] / scnt[g];
    __syncthreads();
    if (tid < G * C) {
        int g = tid / C, c = tid % C;
        float acc = bl[c];
        for (int k = 0; k < D; k++) acc = fmaf(hg[g * D + k], Wl[k * C + c], acc);
        logits[tid] = acc;
    }
    __syncthreads();
    if (tid < G) {
        float m = -1e30f;
        for (int c = 0; c < C; c++) m = fmaxf(m, logits[tid * C + c]);
        float s = 0.0f;
        float e[C];
        for (int c = 0; c < C; c++) { e[c] = expf(logits[tid * C + c] - m); s += e[c]; }
        float inv = 1.0f / s;
        for (int c = 0; c < C; c++) out[tid * C + c] = e[c] * inv;
    }
}

// ---------------- launch --------------------------------------------------------
extern "C" void kernel_launch(void* const* d_in, const int* in_sizes, int n_in,
                              void* d_out, int out_size) {
    const float* x   = (const float*)d_in[0];
    const int*   ei  = (const int*)d_in[1];
    const int*   n2g = (const int*)d_in[2];
    const float* W1  = (const float*)d_in[3];
    const float* b1  = (const float*)d_in[4];
    const float* W2  = (const float*)d_in[5];
    const float* b2  = (const float*)d_in[6];
    const float* Wl  = (const float*)d_in[7];
    const float* bl  = (const float*)d_in[8];
    float* out = (float*)d_out;

    const int N = in_sizes[2];
    const int E = in_sizes[1] / 2;

    float* inq  = nullptr; cudaGetSymbolAddress((void**)&inq,  g_in_isqrt);
    unsigned char* hA = nullptr; cudaGetSymbolAddress((void**)&hA, g_h8A);
    unsigned char* hB = nullptr; cudaGetSymbolAddress((void**)&hB, g_h8B);
    __half* w1h = nullptr; cudaGetSymbolAddress((void**)&w1h, g_W1h);
    __half* w2h = nullptr; cudaGetSymbolAddress((void**)&w2h, g_W2h);
    float* sums = nullptr; cudaGetSymbolAddress((void**)&sums, g_sums);
    int* outc = nullptr; cudaGetSymbolAddress((void**)&outc, g_outcnt);
    int* inc  = nullptr; cudaGetSymbolAddress((void**)&inc,  g_incnt);
    int* rowp = nullptr; cudaGetSymbolAddress((void**)&rowp, g_rowptr);
    int* cur  = nullptr; cudaGetSymbolAddress((void**)&cur,  g_cursor);
    int* csr  = nullptr; cudaGetSymbolAddress((void**)&csr,  g_csr);
    int* bsum = nullptr; cudaGetSymbolAddress((void**)&bsum, g_bsums);

    const int nb = (N + 255) / 256;
    const int ntiles = (N + 127) / 128;
    const int gatherBlocks = (N * 32 + 255) / 256;
    const int smemGemm = 2 * 128 * LDA * (int)sizeof(__half);   // 69632

    static cudaStream_t s1;
    static cudaEvent_t ev_fork, ev_csr;
    static int s_init = 0;
    if (!s_init) {
        cudaFuncSetAttribute(k_gemm_tc,
                             cudaFuncAttributeMaxDynamicSharedMemorySize, smemGemm);
        cudaFuncSetAttribute(k_gemm_tc8,
                             cudaFuncAttributeMaxDynamicSharedMemorySize, smemGemm);
        cudaStreamCreateWithFlags(&s1, cudaStreamNonBlocking);
        cudaEventCreateWithFlags(&ev_fork, cudaEventDisableTiming);
        cudaEventCreateWithFlags(&ev_csr, cudaEventDisableTiming);
        s_init = 1;
    }

    // 1: setup (main)
    k_setup<<<nb, 256>>>(outc, inc, N, sums, W1, W2, w1h, w2h);
    cudaEventRecord(ev_fork, 0);
    cudaStreamWaitEvent(s1, ev_fork, 0);

    // 2: out-degree histogram (main) — only dependency of gemm1
    k_degout<<<(E + 255) / 256, 256>>>(ei, E, outc);
    // 3: in-degree histogram (s1) — feeds CSR chain
    k_degin<<<(E + 255) / 256, 256, 0, s1>>>(ei, E, inc);

    // 4 (profiled slot): layer-1 GEMM (3 CTAs/SM, batched loads)
    k_gemm_tc<<<ntiles, 256, smemGemm>>>(x, outc, w1h, hA, N);

    // 5..7: CSR chain on s1
    k_scan1<<<nb, 256, 0, s1>>>(inc, N, bsum);
    k_scan3<<<nb, 256, 0, s1>>>(inc, N, nb, E, bsum, rowp, cur, inq);
    k_fill<<<(E + 255) / 256, 256, 0, s1>>>(ei, E, cur, csr);

    cudaEventRecord(ev_csr, s1);
    cudaStreamWaitEvent(0, ev_csr, 0);

    // 8..10: gather1 (folds oq), gemm2, gather2 + fused pool
    k_gather<1, 0><<<gatherBlocks, 256>>>(csr, rowp, hA, inq, b1, outc, hB, N, n2g);
    k_gemm_tc8<<<ntiles, 256, smemGemm>>>(hB, w2h, hA, N);
    k_gather<0, 1><<<gatherBlocks, 256>>>(csr, rowp, hA, inq, b2, outc, hB, N, n2g);

    // 11: head
    k_final<<<1, 128>>>(Wl, bl, n2g, N, out);
}